// round 7
// baseline (speedup 1.0000x reference)
#include <cuda_runtime.h>
#include <cuda_bf16.h>
#include <math.h>
#include <stdint.h>

#define NTOK 2048
#define BATCH 2
#define DIMV 768
#define NHEAD 12
#define HDIM 64
#define KNN 32
#define DFF 3072
#define MROWS 4096   // BATCH*NTOK
#define QMAX 16256.0f

// ---------------------------------------------------------------------------
// one big byte arena, carved in kernel_launch (all offsets 128B-aligned)
#define ARENA_BYTES 170000000ull
__device__ __align__(128) char g_arena[ARENA_BYTES];
__device__ int   g_idx[MROWS * KNN];
__device__ float g_dist[MROWS * KNN];

// ---------------------------------------------------------------------------
__device__ __forceinline__ float gelu_f(float v) {
    return 0.5f * v * (1.f + erff(v * 0.70710678118654752f));
}
__device__ __forceinline__ void quant_limbs(float v, float inv_s, char& q1c, char& q0c) {
    int q = __float2int_rn(v * inv_s);
    q = max(-16256, min(16256, q));
    int q1 = (q + 64) >> 7;
    int q0 = q - (q1 << 7);
    q1c = (char)q1; q0c = (char)q0;
}

// ---------------------------------------------------------------------------
// weight prep: per-column absmax -> scale; qkv variant also concats bias
__global__ void __launch_bounds__(256) wprep_qkv_kernel(
    const float* __restrict__ Wq, const float* __restrict__ Wk, const float* __restrict__ Wv,
    const float* __restrict__ bq, const float* __restrict__ bk, const float* __restrict__ bv,
    float* __restrict__ sB, float* __restrict__ bqkv)
{
    int j = blockIdx.x * 256 + threadIdx.x;          // 0..2303
    int w = j / 768, col = j - w * 768;
    const float* W = (w == 0) ? Wq : (w == 1) ? Wk : Wv;
    const float* bb = (w == 0) ? bq : (w == 1) ? bk : bv;
    float mx = 0.f;
    for (int k = 0; k < 768; k++) mx = fmaxf(mx, fabsf(W[(size_t)k * 768 + col]));
    sB[j] = fmaxf(mx, 1e-20f) / QMAX;
    bqkv[j] = bb[col];
}

__global__ void __launch_bounds__(256) wprep_rest_kernel(
    const float* __restrict__ Wo, const float* __restrict__ W1, const float* __restrict__ W2,
    float* __restrict__ sBo, float* __restrict__ sB1, float* __restrict__ sB2)
{
    int j = blockIdx.x * 256 + threadIdx.x;          // 0..4607
    const float* W; int col, K, Nc; float* out;
    if (j < 768)       { W = Wo; col = j;        K = 768;  Nc = 768;  out = sBo + col; }
    else if (j < 3840) { W = W1; col = j - 768;  K = 768;  Nc = 3072; out = sB1 + col; }
    else               { W = W2; col = j - 3840; K = 3072; Nc = 768;  out = sB2 + col; }
    float mx = 0.f;
    for (int k = 0; k < K; k++) mx = fmaxf(mx, fabsf(W[(size_t)k * Nc + col]));
    *out = fmaxf(mx, 1e-20f) / QMAX;
}

// transpose+quantize: W[K][Nc] -> limb planes [rowOff+Nc][Kd] bytes
__device__ __forceinline__ void wq_tile(const float* W, const float* sB,
    char* o1, char* o0, int Nc, int Kd, int rowOff, int n0, int k0, int tid)
{
    __shared__ char s1[32][33], s0[32][33];
    int tx = tid & 31, tyg = tid >> 5;
#pragma unroll
    for (int j = 0; j < 4; j++) {
        int kl = tyg * 4 + j;
        int n = n0 + tx;
        float inv = __fdividef(1.0f, sB[rowOff + n]);
        float v = W[(size_t)(k0 + kl) * Nc + n];
        quant_limbs(v, inv, s1[kl][tx], s0[kl][tx]);
    }
    __syncthreads();
#pragma unroll
    for (int j = 0; j < 4; j++) {
        int nl = tyg * 4 + j;
        size_t oidx = (size_t)(rowOff + n0 + nl) * Kd + k0 + tx;
        o1[oidx] = s1[tx][nl];
        o0[oidx] = s0[tx][nl];
    }
}

__global__ void __launch_bounds__(256) wquantT3_kernel(
    const float* __restrict__ Wq, const float* __restrict__ Wk, const float* __restrict__ Wv,
    const float* __restrict__ sB, char* __restrict__ o1, char* __restrict__ o0)
{
    int z = blockIdx.z;
    const float* W = (z == 0) ? Wq : (z == 1) ? Wk : Wv;
    wq_tile(W, sB, o1, o0, 768, 768, z * 768, blockIdx.x * 32, blockIdx.y * 32, threadIdx.x);
}

__global__ void __launch_bounds__(256) wquantT_kernel(
    const float* __restrict__ W, const float* __restrict__ sB,
    char* __restrict__ o1, char* __restrict__ o0, int Nc, int Kd)
{
    wq_tile(W, sB, o1, o0, Nc, Kd, 0, blockIdx.x * 32, blockIdx.y * 32, threadIdx.x);
}

// ---------------------------------------------------------------------------
// LayerNorm (+time emb) -> int8 limb planes + per-row scale
__global__ void __launch_bounds__(384) ln_quant_kernel(const float* __restrict__ x,
    const float* __restrict__ g, const float* __restrict__ be,
    const float* __restrict__ temb, char* __restrict__ o1, char* __restrict__ o0,
    float* __restrict__ sA)
{
    __shared__ float sb[13];
    int row = blockIdx.x, tid = threadIdx.x;
    int lane = tid & 31, w = tid >> 5;
    float2 xv = *(const float2*)(x + (size_t)row * DIMV + 2 * tid);
    float s = xv.x + xv.y;
#pragma unroll
    for (int o = 16; o; o >>= 1) s += __shfl_xor_sync(0xffffffffu, s, o);
    if (lane == 0) sb[w] = s;
    __syncthreads();
    if (w == 0) {
        float r = (lane < 12) ? sb[lane] : 0.f;
#pragma unroll
        for (int o = 16; o; o >>= 1) r += __shfl_xor_sync(0xffffffffu, r, o);
        if (lane == 0) sb[12] = r;
    }
    __syncthreads();
    float mu = sb[12] * (1.0f / DIMV);
    float dx = xv.x - mu, dy = xv.y - mu;
    float vs = dx * dx + dy * dy;
    __syncthreads();
#pragma unroll
    for (int o = 16; o; o >>= 1) vs += __shfl_xor_sync(0xffffffffu, vs, o);
    if (lane == 0) sb[w] = vs;
    __syncthreads();
    if (w == 0) {
        float r = (lane < 12) ? sb[lane] : 0.f;
#pragma unroll
        for (int o = 16; o; o >>= 1) r += __shfl_xor_sync(0xffffffffu, r, o);
        if (lane == 0) sb[12] = r;
    }
    __syncthreads();
    float inv = rsqrtf(sb[12] * (1.0f / DIMV) + 1e-5f);
    int b = row >> 11;
    int i0 = 2 * tid;
    float v0 = dx * inv * g[i0] + be[i0];
    float v1 = dy * inv * g[i0 + 1] + be[i0 + 1];
    if (temb) { v0 += temb[b * DIMV + i0]; v1 += temb[b * DIMV + i0 + 1]; }
    // row absmax
    float mx = fmaxf(fabsf(v0), fabsf(v1));
    __syncthreads();
#pragma unroll
    for (int o = 16; o; o >>= 1) mx = fmaxf(mx, __shfl_xor_sync(0xffffffffu, mx, o));
    if (lane == 0) sb[w] = mx;
    __syncthreads();
    if (w == 0) {
        float r = (lane < 12) ? sb[lane] : 0.f;
#pragma unroll
        for (int o = 16; o; o >>= 1) r = fmaxf(r, __shfl_xor_sync(0xffffffffu, r, o));
        if (lane == 0) sb[12] = r;
    }
    __syncthreads();
    float rmax = fmaxf(sb[12], 1e-20f);
    float invs = QMAX / rmax;
    char a1, a0, b1, b0;
    quant_limbs(v0, invs, a1, a0);
    quant_limbs(v1, invs, b1, b0);
    size_t oi = (size_t)row * DIMV + i0;
    *(char2*)(o1 + oi) = make_char2(a1, b1);
    *(char2*)(o0 + oi) = make_char2(a0, b0);
    if (tid == 0) sA[row] = rmax / QMAX;
}

// ---------------------------------------------------------------------------
// int8 limb GEMM: C = sA sB^T * (16384 hh + 128 cx + ll) + bias (+gelu)(+res)
// A planes [M][K], B planes [Nc][K]. Block 128x64, 8 warps (64x16/warp),
// BK=64, 4-stage cp.async.
// ---------------------------------------------------------------------------
#define O_A1 0
#define O_A0 8192
#define O_B1 16384
#define O_B0 20480
#define STG_BYTES 24576
#define GEMM_SMEM (4 * STG_BYTES)   // 96KB

__device__ __forceinline__ void cp16s(uint32_t sdst, const void* src) {
    asm volatile("cp.async.cg.shared.global [%0], [%1], 16;" :: "r"(sdst), "l"(src));
}
#define LDSM4(r, addr)                                                        \
    asm volatile("ldmatrix.sync.aligned.m8n8.x4.shared.b16 {%0,%1,%2,%3}, [%4];" \
        : "=r"((r)[0]), "=r"((r)[1]), "=r"((r)[2]), "=r"((r)[3]) : "r"(addr))
#define MMA_S8(d, a, b0, b1)                                                  \
    asm volatile(                                                             \
        "mma.sync.aligned.m16n8k32.row.col.s32.s8.s8.s32 "                    \
        "{%0,%1,%2,%3},{%4,%5,%6,%7},{%8,%9},{%0,%1,%2,%3};"                  \
        : "+r"((d)[0]), "+r"((d)[1]), "+r"((d)[2]), "+r"((d)[3])              \
        : "r"((a)[0]), "r"((a)[1]), "r"((a)[2]), "r"((a)[3]), "r"(b0), "r"(b1))

__global__ void __launch_bounds__(256, 1) s8_gemm_kernel(
    const char* __restrict__ A1, const char* __restrict__ A0,
    const char* __restrict__ B1, const char* __restrict__ B0,
    const float* __restrict__ sA, const float* __restrict__ sB,
    const float* __restrict__ bias, const float* __restrict__ res,
    float* __restrict__ Cf, int Nc, int K, int act)
{
    extern __shared__ __align__(128) char smc[];
    const int tid = threadIdx.x;
    const int warp = tid >> 5, lane = tid & 31;
    const int wm = warp & 1, wn = warp >> 1;          // 2x4 warp grid
    const int g = lane >> 2, t = lane & 3;
    const int bm = blockIdx.y * 128, bn = blockIdx.x * 64;
    const int nk = K >> 6;                            // BK=64

    uint32_t sbase;
    asm("{ .reg .u64 tt; cvta.to.shared.u64 tt, %1; cvt.u32.u64 %0, tt; }"
        : "=r"(sbase) : "l"(smc));

    // ldmatrix lane addressing (64B rows, 16B-chunk XOR swizzle)
    const int arl = lane & 15, aqb = lane >> 4;
    const int arsw = (arl >> 1) & 3;
    uint32_t aoff[4], aq[2];
#pragma unroll
    for (int mi = 0; mi < 4; mi++)
        aoff[mi] = (uint32_t)(wm * 64 + mi * 16 + arl) * 64u;
#pragma unroll
    for (int ks = 0; ks < 2; ks++)
        aq[ks] = (uint32_t)(((2 * ks + aqb) ^ arsw) << 4);
    const int nrl = (lane & 7) + ((lane >> 4) << 3);
    const int bqb = (lane >> 3) & 1;
    const int brsw = (nrl >> 1) & 3;
    const uint32_t boff = (uint32_t)(wn * 16 + nrl) * 64u;
    uint32_t bq[2];
#pragma unroll
    for (int ks = 0; ks < 2; ks++)
        bq[ks] = (uint32_t)(((2 * ks + bqb) ^ brsw) << 4);

    int hh[4][2][4], cx[4][2][4], ll[4][2][4];
#pragma unroll
    for (int mi = 0; mi < 4; mi++)
#pragma unroll
        for (int ni = 0; ni < 2; ni++)
#pragma unroll
            for (int e = 0; e < 4; e++) { hh[mi][ni][e] = 0; cx[mi][ni][e] = 0; ll[mi][ni][e] = 0; }

    auto load_stage = [&](int buf, int it) {
        if (it < nk) {
            uint32_t st = sbase + buf * STG_BYTES;
            int kb = it * 64;
#pragma unroll
            for (int r2 = 0; r2 < 2; r2++) {
                int idx = tid + r2 * 256;
                int m = idx >> 2, q = idx & 3;
                uint32_t woff = (uint32_t)(m * 64 + ((q ^ ((m >> 1) & 3)) << 4));
                size_t ga = (size_t)(bm + m) * K + kb + q * 16;
                cp16s(st + O_A1 + woff, A1 + ga);
                cp16s(st + O_A0 + woff, A0 + ga);
            }
            {
                int n = tid >> 2, q = tid & 3;
                uint32_t woff = (uint32_t)(n * 64 + ((q ^ ((n >> 1) & 3)) << 4));
                size_t gb = (size_t)(bn + n) * K + kb + q * 16;
                cp16s(st + O_B1 + woff, B1 + gb);
                cp16s(st + O_B0 + woff, B0 + gb);
            }
        }
        asm volatile("cp.async.commit_group;");
    };

    load_stage(0, 0);
    load_stage(1, 1);
    load_stage(2, 2);

    for (int it = 0; it < nk; it++) {
        asm volatile("cp.async.wait_group 2;");
        __syncthreads();
        load_stage((it + 3) & 3, it + 3);

        uint32_t st = sbase + (it & 3) * STG_BYTES;
#pragma unroll
        for (int ks = 0; ks < 2; ks++) {
            uint32_t fA1[4][4], fA0[4][4], fB1[4], fB0[4];
#pragma unroll
            for (int mi = 0; mi < 4; mi++)
                LDSM4(fA1[mi], st + O_A1 + aoff[mi] + aq[ks]);
            LDSM4(fB1, st + O_B1 + boff + bq[ks]);
#pragma unroll
            for (int mi = 0; mi < 4; mi++)
#pragma unroll
                for (int ni = 0; ni < 2; ni++)
                    MMA_S8(hh[mi][ni], fA1[mi], fB1[2 * ni], fB1[2 * ni + 1]);
            LDSM4(fB0, st + O_B0 + boff + bq[ks]);
#pragma unroll
            for (int mi = 0; mi < 4; mi++)
#pragma unroll
                for (int ni = 0; ni < 2; ni++)
                    MMA_S8(cx[mi][ni], fA1[mi], fB0[2 * ni], fB0[2 * ni + 1]);
#pragma unroll
            for (int mi = 0; mi < 4; mi++)
                LDSM4(fA0[mi], st + O_A0 + aoff[mi] + aq[ks]);
#pragma unroll
            for (int mi = 0; mi < 4; mi++)
#pragma unroll
                for (int ni = 0; ni < 2; ni++)
                    MMA_S8(cx[mi][ni], fA0[mi], fB1[2 * ni], fB1[2 * ni + 1]);
#pragma unroll
            for (int mi = 0; mi < 4; mi++)
#pragma unroll
                for (int ni = 0; ni < 2; ni++)
                    MMA_S8(ll[mi][ni], fA0[mi], fB0[2 * ni], fB0[2 * ni + 1]);
        }
    }

    // epilogue
#pragma unroll
    for (int mi = 0; mi < 4; mi++) {
#pragma unroll
        for (int ni = 0; ni < 2; ni++) {
            int col = bn + wn * 16 + ni * 8 + 2 * t;
            float2 sb2 = *(const float2*)(sB + col);
            float2 bb = *(const float2*)(bias + col);
#pragma unroll
            for (int hf = 0; hf < 2; hf++) {
                int r = bm + wm * 64 + mi * 16 + g + hf * 8;
                float sa = sA[r];
                float vx = sa * sb2.x * (16384.f * (float)hh[mi][ni][2 * hf]
                          + 128.f * (float)cx[mi][ni][2 * hf]
                          + (float)ll[mi][ni][2 * hf]) + bb.x;
                float vy = sa * sb2.y * (16384.f * (float)hh[mi][ni][2 * hf + 1]
                          + 128.f * (float)cx[mi][ni][2 * hf + 1]
                          + (float)ll[mi][ni][2 * hf + 1]) + bb.y;
                if (act) { vx = gelu_f(vx); vy = gelu_f(vy); }
                if (res) {
                    const float2 rr = *(const float2*)(res + (size_t)r * Nc + col);
                    vx += rr.x; vy += rr.y;
                }
                float2 o; o.x = vx; o.y = vy;
                *(float2*)(Cf + (size_t)r * Nc + col) = o;
            }
        }
    }
}

// ---------------------------------------------------------------------------
// ffn row quant: fp32 [row][3072] -> limb planes + scale
__global__ void __launch_bounds__(256) ffn_quant_kernel(const float* __restrict__ f,
    char* __restrict__ o1, char* __restrict__ o0, float* __restrict__ sA)
{
    __shared__ float sb[9];
    int row = blockIdx.x, tid = threadIdx.x;
    int lane = tid & 31, w = tid >> 5;
    const float4* base = (const float4*)(f + (size_t)row * DFF);
    float mx = 0.f;
#pragma unroll
    for (int i = 0; i < 3; i++) {
        float4 v = base[tid + i * 256];
        mx = fmaxf(mx, fmaxf(fmaxf(fabsf(v.x), fabsf(v.y)), fmaxf(fabsf(v.z), fabsf(v.w))));
    }
#pragma unroll
    for (int o = 16; o; o >>= 1) mx = fmaxf(mx, __shfl_xor_sync(0xffffffffu, mx, o));
    if (lane == 0) sb[w] = mx;
    __syncthreads();
    if (w == 0) {
        float r = (lane < 8) ? sb[lane] : 0.f;
#pragma unroll
        for (int o = 4; o; o >>= 1) r = fmaxf(r, __shfl_xor_sync(0xffffffffu, r, o));
        if (lane == 0) sb[8] = r;
    }
    __syncthreads();
    float rmax = fmaxf(sb[8], 1e-20f);
    float inv = QMAX / rmax;
    uint32_t* p1 = (uint32_t*)(o1 + (size_t)row * DFF);
    uint32_t* p0 = (uint32_t*)(o0 + (size_t)row * DFF);
#pragma unroll
    for (int i = 0; i < 3; i++) {
        float4 v = base[tid + i * 256];
        char a1, a0, b1, b0, c1, c0, d1, d0;
        quant_limbs(v.x, inv, a1, a0);
        quant_limbs(v.y, inv, b1, b0);
        quant_limbs(v.z, inv, c1, c0);
        quant_limbs(v.w, inv, d1, d0);
        p1[tid + i * 256] = (uint32_t)(uint8_t)a1 | ((uint32_t)(uint8_t)b1 << 8)
                          | ((uint32_t)(uint8_t)c1 << 16) | ((uint32_t)(uint8_t)d1 << 24);
        p0[tid + i * 256] = (uint32_t)(uint8_t)a0 | ((uint32_t)(uint8_t)b0 << 8)
                          | ((uint32_t)(uint8_t)c0 << 16) | ((uint32_t)(uint8_t)d0 << 24);
    }
    if (tid == 0) sA[row] = rmax / QMAX;
}

// ---------------------------------------------------------------------------
// Poincare distance + top-KNN per row
__global__ void __launch_bounds__(256) topk_kernel(const float* __restrict__ pos,
    const float* __restrict__ cptr, int* __restrict__ idxo, float* __restrict__ disto)
{
    __shared__ float arg[NTOK];
    __shared__ float rv[8];
    __shared__ int ri[8];
    int row = blockIdx.x;
    int b = row >> 11, i = row & (NTOK - 1);
    float c = cptr[0];
    float inv_sqc = rsqrtf(c);
    const float* pb = pos + (size_t)b * NTOK * 2;
    float yx = pb[i * 2], yy = pb[i * 2 + 1];
    float denY = 1.f - c * (yx * yx + yy * yy);
    for (int j = threadIdx.x; j < NTOK; j += 256) {
        float xx = pb[j * 2], xy = pb[j * 2 + 1];
        float dx = xx - yx, dy = xy - yy;
        float num = 2.f * c * (dx * dx + dy * dy);
        float den = (1.f - c * (xx * xx + xy * xy)) * denY;
        arg[j] = fmaxf(1.f + num / (den + 1e-8f), 1.f);
    }
    __syncthreads();
    int lane = threadIdx.x & 31, w = threadIdx.x >> 5;
    for (int sel = 0; sel < KNN; sel++) {
        float bv = 3.4e38f; int bi = 0x7fffffff;
        for (int j = threadIdx.x; j < NTOK; j += 256) {
            float a = arg[j];
            if (a < bv) { bv = a; bi = j; }
        }
#pragma unroll
        for (int o = 16; o; o >>= 1) {
            float ov = __shfl_xor_sync(0xffffffffu, bv, o);
            int   oi = __shfl_xor_sync(0xffffffffu, bi, o);
            if (ov < bv || (ov == bv && oi < bi)) { bv = ov; bi = oi; }
        }
        if (lane == 0) { rv[w] = bv; ri[w] = bi; }
        __syncthreads();
        if (threadIdx.x == 0) {
            float fv = rv[0]; int fi = ri[0];
            for (int t2 = 1; t2 < 8; t2++)
                if (rv[t2] < fv || (rv[t2] == fv && ri[t2] < fi)) { fv = rv[t2]; fi = ri[t2]; }
            idxo[(size_t)row * KNN + sel] = fi;
            disto[(size_t)row * KNN + sel] = acoshf(fv) * inv_sqc;
            arg[fi] = 3.4e38f;
        }
        __syncthreads();
    }
}

// ---------------------------------------------------------------------------
// kNN attention over fused qkv [row][2304]; int8-limb output + row scale
__global__ void __launch_bounds__(384) attn_quant_kernel(const float* __restrict__ qkv,
    const int* __restrict__ idx, const float* __restrict__ dist,
    const float* __restrict__ log_tau,
    char* __restrict__ o1, char* __restrict__ o0, float* __restrict__ sA)
{
    __shared__ int sidx[KNN];
    __shared__ float sgeo[KNN];
    __shared__ float smax[13];
    int row = blockIdx.x;
    int lane = threadIdx.x & 31, h = threadIdx.x >> 5;
    float invtau = 1.f / (expf(log_tau[0]) + 1e-8f);
    if (threadIdx.x < KNN) {
        sidx[threadIdx.x] = idx[(size_t)row * KNN + threadIdx.x];
        sgeo[threadIdx.x] = -dist[(size_t)row * KNN + threadIdx.x] * invtau;
    }
    __syncthreads();
    int b = row >> 11;
    const float* qp = qkv + (size_t)row * 2304 + h * HDIM;
    float q0 = qp[2 * lane], q1 = qp[2 * lane + 1];
    const float* kb = qkv + (size_t)b * NTOK * 2304 + 768 + h * HDIM;
    const float* vb = qkv + (size_t)b * NTOK * 2304 + 1536 + h * HDIM;
    float myscore = 0.f;
#pragma unroll 4
    for (int j = 0; j < KNN; j++) {
        const float* kp = kb + (size_t)sidx[j] * 2304;
        float p = q0 * kp[2 * lane] + q1 * kp[2 * lane + 1];
#pragma unroll
        for (int o = 16; o; o >>= 1) p += __shfl_xor_sync(0xffffffffu, p, o);
        if (lane == j) myscore = p * 0.125f + sgeo[j];
    }
    float m = myscore;
#pragma unroll
    for (int o = 16; o; o >>= 1) m = fmaxf(m, __shfl_xor_sync(0xffffffffu, m, o));
    float e = expf(myscore - m);
    float s = e;
#pragma unroll
    for (int o = 16; o; o >>= 1) s += __shfl_xor_sync(0xffffffffu, s, o);
    float p = e / s;
    float v0 = 0.f, v1 = 0.f;
#pragma unroll 4
    for (int j = 0; j < KNN; j++) {
        float pj = __shfl_sync(0xffffffffu, p, j);
        const float* vp = vb + (size_t)sidx[j] * 2304;
        v0 += pj * vp[2 * lane]; v1 += pj * vp[2 * lane + 1];
    }
    // block max + quant
    float mx = fmaxf(fabsf(v0), fabsf(v1));
#pragma unroll
    for (int o = 16; o; o >>= 1) mx = fmaxf(mx, __shfl_xor_sync(0xffffffffu, mx, o));
    if (lane == 0) smax[h] = mx;
    __syncthreads();
    if (h == 0) {
        float r = (lane < 12) ? smax[lane] : 0.f;
#pragma unroll
        for (int o = 16; o; o >>= 1) r = fmaxf(r, __shfl_xor_sync(0xffffffffu, r, o));
        if (lane == 0) smax[12] = r;
    }
    __syncthreads();
    float rmax = fmaxf(smax[12], 1e-20f);
    float inv = QMAX / rmax;
    char a1, a0, b1c, b0c;
    quant_limbs(v0, inv, a1, a0);
    quant_limbs(v1, inv, b1c, b0c);
    size_t oi = (size_t)row * DIMV + h * HDIM + 2 * lane;
    *(char2*)(o1 + oi) = make_char2(a1, b1c);
    *(char2*)(o0 + oi) = make_char2(a0, b0c);
    if (threadIdx.x == 0) sA[row] = rmax / QMAX;
}

// ---------------------------------------------------------------------------
extern "C" void kernel_launch(void* const* d_in, const int* in_sizes, int n_in,
                              void* d_out, int out_size)
{
    const float* x    = (const float*)d_in[0];
    const float* pos  = (const float*)d_in[1];
    const float* c    = (const float*)d_in[2];
    const float* temb = (const float*)d_in[3];
    const float* Wq = (const float*)d_in[4],  *bq = (const float*)d_in[5];
    const float* Wk = (const float*)d_in[6],  *bk = (const float*)d_in[7];
    const float* Wv = (const float*)d_in[8],  *bv = (const float*)d_in[9];
    const float* Wo = (const float*)d_in[10], *bo = (const float*)d_in[11];
    const float* W1 = (const float*)d_in[12], *b1 = (const float*)d_in[13];
    const float* W2 = (const float*)d_in[14], *b2 = (const float*)d_in[15];
    const float* g1 = (const float*)d_in[16], *be1 = (const float*)d_in[17];
    const float* g2 = (const float*)d_in[18], *be2 = (const float*)d_in[19];
    const float* log_tau = (const float*)d_in[20];
    float* out = (float*)d_out;

    char* arena; cudaGetSymbolAddress((void**)&arena, g_arena);
    int* idxp;   cudaGetSymbolAddress((void**)&idxp, g_idx);
    float* distp;cudaGetSymbolAddress((void**)&distp, g_dist);

    char* p = arena;
    auto carve = [&](size_t bytes) { char* r = p; p += (bytes + 127) & ~(size_t)127; return r; };
    char* h1   = carve((size_t)MROWS * 768);
    char* h0   = carve((size_t)MROWS * 768);
    char* att1 = carve((size_t)MROWS * 768);
    char* att0 = carve((size_t)MROWS * 768);
    char* h21  = carve((size_t)MROWS * 768);
    char* h20  = carve((size_t)MROWS * 768);
    char* ffn1 = carve((size_t)MROWS * 3072);
    char* ffn0 = carve((size_t)MROWS * 3072);
    char* wqkv1 = carve((size_t)2304 * 768);
    char* wqkv0 = carve((size_t)2304 * 768);
    char* wo1  = carve((size_t)768 * 768);
    char* wo0  = carve((size_t)768 * 768);
    char* w11  = carve((size_t)3072 * 768);
    char* w10  = carve((size_t)3072 * 768);
    char* w21  = carve((size_t)768 * 3072);
    char* w20  = carve((size_t)768 * 3072);
    float* qkv   = (float*)carve((size_t)MROWS * 2304 * 4);
    float* x2    = (float*)carve((size_t)MROWS * 768 * 4);
    float* ffn_f = (float*)carve((size_t)MROWS * 3072 * 4);
    float* sAh   = (float*)carve(MROWS * 4);
    float* sAatt = (float*)carve(MROWS * 4);
    float* sAh2  = (float*)carve(MROWS * 4);
    float* sAffn = (float*)carve(MROWS * 4);
    float* sBqkv = (float*)carve(2304 * 4);
    float* sBo   = (float*)carve(768 * 4);
    float* sB1   = (float*)carve(3072 * 4);
    float* sB2   = (float*)carve(768 * 4);
    float* bqkv  = (float*)carve(2304 * 4);

    cudaFuncSetAttribute(s8_gemm_kernel,
                         cudaFuncAttributeMaxDynamicSharedMemorySize, GEMM_SMEM);

    // launches 1-3, then QKV GEMM as launch 4 (= ncu capture slot)
    ln_quant_kernel<<<MROWS, 384>>>(x, g1, be1, temb, h1, h0, sAh);
    wprep_qkv_kernel<<<9, 256>>>(Wq, Wk, Wv, bq, bk, bv, sBqkv, bqkv);
    wquantT3_kernel<<<dim3(24, 24, 3), 256>>>(Wq, Wk, Wv, sBqkv, wqkv1, wqkv0);
    s8_gemm_kernel<<<dim3(36, 32), 256, GEMM_SMEM>>>(h1, h0, wqkv1, wqkv0,
        sAh, sBqkv, bqkv, nullptr, qkv, 2304, 768, 0);

    topk_kernel<<<MROWS, 256>>>(pos, c, idxp, distp);
    attn_quant_kernel<<<MROWS, 384>>>(qkv, idxp, distp, log_tau, att1, att0, sAatt);

    wprep_rest_kernel<<<18, 256>>>(Wo, W1, W2, sBo, sB1, sB2);
    wquantT_kernel<<<dim3(24, 24), 256>>>(Wo, sBo, wo1, wo0, 768, 768);
    wquantT_kernel<<<dim3(96, 24), 256>>>(W1, sB1, w11, w10, 3072, 768);
    wquantT_kernel<<<dim3(24, 96), 256>>>(W2, sB2, w21, w20, 768, 3072);

    // x2 = x + att @ Wo
    s8_gemm_kernel<<<dim3(12, 32), 256, GEMM_SMEM>>>(att1, att0, wo1, wo0,
        sAatt, sBo, bo, x, x2, 768, 768, 0);
    ln_quant_kernel<<<MROWS, 384>>>(x2, g2, be2, nullptr, h21, h20, sAh2);

    // ffn_f = gelu(h2 @ W1)
    s8_gemm_kernel<<<dim3(48, 32), 256, GEMM_SMEM>>>(h21, h20, w11, w10,
        sAh2, sB1, b1, nullptr, ffn_f, 3072, 768, 1);
    ffn_quant_kernel<<<MROWS, 256>>>(ffn_f, ffn1, ffn0, sAffn);

    // out = x2 + ffn @ W2
    s8_gemm_kernel<<<dim3(12, 32), 256, GEMM_SMEM>>>(ffn1, ffn0, w21, w20,
        sAffn, sB2, b2, x2, out, 768, 3072, 0);
}

// round 8
// speedup vs baseline: 1.4196x; 1.4196x over previous
#include <cuda_runtime.h>
#include <cuda_bf16.h>
#include <math.h>
#include <stdint.h>

#define NTOK 2048
#define BATCH 2
#define DIMV 768
#define NHEAD 12
#define HDIM 64
#define KNN 32
#define DFF 3072
#define MROWS 4096   // BATCH*NTOK
#define QMAX 16256.0f
#define PSTRIDE 8192

// ---------------------------------------------------------------------------
#define ARENA_BYTES 172000000ull
__device__ __align__(128) char g_arena[ARENA_BYTES];
__device__ int   g_idx[MROWS * KNN];
__device__ float g_dist[MROWS * KNN];

// ---------------------------------------------------------------------------
__device__ __forceinline__ float gelu_f(float v) {
    return 0.5f * v * (1.f + erff(v * 0.70710678118654752f));
}
__device__ __forceinline__ void quant_limbs(float v, float inv_s, char& q1c, char& q0c) {
    int q = __float2int_rn(v * inv_s);
    q = max(-16256, min(16256, q));
    int q1 = (q + 64) >> 7;
    int q0 = q - (q1 << 7);
    q1c = (char)q1; q0c = (char)q0;
}

// ---------------------------------------------------------------------------
// parallel per-column absmax, 8 K-chunks; qkv variant also concats bias
__global__ void __launch_bounds__(256) wpmax_qkv_kernel(
    const float* __restrict__ Wq, const float* __restrict__ Wk, const float* __restrict__ Wv,
    const float* __restrict__ bq, const float* __restrict__ bk, const float* __restrict__ bv,
    float* __restrict__ partial, float* __restrict__ bqkv)
{
    int col = blockIdx.x * 256 + threadIdx.x;        // 0..2303
    int w = col / 768, c = col - w * 768;
    const float* W = (w == 0) ? Wq : (w == 1) ? Wk : Wv;
    int k0 = blockIdx.y * 96;
    float mx = 0.f;
#pragma unroll 8
    for (int k = k0; k < k0 + 96; k++) mx = fmaxf(mx, fabsf(W[(size_t)k * 768 + c]));
    partial[blockIdx.y * PSTRIDE + col] = mx;
    if (blockIdx.y == 0)
        bqkv[col] = ((w == 0) ? bq : (w == 1) ? bk : bv)[c];
}

__global__ void __launch_bounds__(256) wpmax_rest_kernel(
    const float* __restrict__ Wo, const float* __restrict__ W1, const float* __restrict__ W2,
    float* __restrict__ partial)
{
    int j = blockIdx.x * 256 + threadIdx.x;          // 0..4607
    const float* W; int c, K, Nc;
    if (j < 768)       { W = Wo; c = j;        K = 768;  Nc = 768;  }
    else if (j < 3840) { W = W1; c = j - 768;  K = 768;  Nc = 3072; }
    else               { W = W2; c = j - 3840; K = 3072; Nc = 768;  }
    int chunk = K >> 3;
    int k0 = blockIdx.y * chunk;
    float mx = 0.f;
#pragma unroll 8
    for (int k = k0; k < k0 + chunk; k++) mx = fmaxf(mx, fabsf(W[(size_t)k * Nc + c]));
    partial[blockIdx.y * PSTRIDE + 2304 + j] = mx;
}

// transpose+quantize tile; reduces partial->scale inline, writes sB (redundant
// identical writes from k0==0 blocks; benign)
__device__ __forceinline__ void wq_tile(const float* W, const float* partial,
    int pcolOff, float* sBout, char* o1, char* o0, int Nc, int Kd, int rowOff,
    int n0, int k0, int tid)
{
    __shared__ char s1[32][33], s0[32][33];
    int tx = tid & 31, tyg = tid >> 5;
    int n = n0 + tx;
    float mx = 0.f;
#pragma unroll
    for (int j = 0; j < 8; j++) mx = fmaxf(mx, partial[j * PSTRIDE + pcolOff + n]);
    mx = fmaxf(mx, 1e-20f);
    float inv = QMAX / mx;
    if (k0 == 0 && tyg == 0) sBout[rowOff + n] = mx / QMAX;
#pragma unroll
    for (int j = 0; j < 4; j++) {
        int kl = tyg * 4 + j;
        float v = W[(size_t)(k0 + kl) * Nc + n];
        quant_limbs(v, inv, s1[kl][tx], s0[kl][tx]);
    }
    __syncthreads();
#pragma unroll
    for (int j = 0; j < 4; j++) {
        int nl = tyg * 4 + j;
        size_t oidx = (size_t)(rowOff + n0 + nl) * Kd + k0 + tx;
        o1[oidx] = s1[tx][nl];
        o0[oidx] = s0[tx][nl];
    }
}

__global__ void __launch_bounds__(256) wquantT3_kernel(
    const float* __restrict__ Wq, const float* __restrict__ Wk, const float* __restrict__ Wv,
    const float* __restrict__ partial, float* __restrict__ sB,
    char* __restrict__ o1, char* __restrict__ o0)
{
    int z = blockIdx.z;
    const float* W = (z == 0) ? Wq : (z == 1) ? Wk : Wv;
    wq_tile(W, partial, z * 768, sB, o1, o0, 768, 768, z * 768,
            blockIdx.x * 32, blockIdx.y * 32, threadIdx.x);
}

__global__ void __launch_bounds__(256) wquantT_kernel(
    const float* __restrict__ W, const float* __restrict__ partial, int pcolOff,
    float* __restrict__ sB, char* __restrict__ o1, char* __restrict__ o0, int Nc, int Kd)
{
    wq_tile(W, partial, pcolOff, sB, o1, o0, Nc, Kd, 0,
            blockIdx.x * 32, blockIdx.y * 32, threadIdx.x);
}

// ---------------------------------------------------------------------------
// LayerNorm (+time emb) -> int8 limb planes + per-row scale
__global__ void __launch_bounds__(384) ln_quant_kernel(const float* __restrict__ x,
    const float* __restrict__ g, const float* __restrict__ be,
    const float* __restrict__ temb, char* __restrict__ o1, char* __restrict__ o0,
    float* __restrict__ sA)
{
    __shared__ float sb[13];
    int row = blockIdx.x, tid = threadIdx.x;
    int lane = tid & 31, w = tid >> 5;
    float2 xv = *(const float2*)(x + (size_t)row * DIMV + 2 * tid);
    float s = xv.x + xv.y;
#pragma unroll
    for (int o = 16; o; o >>= 1) s += __shfl_xor_sync(0xffffffffu, s, o);
    if (lane == 0) sb[w] = s;
    __syncthreads();
    if (w == 0) {
        float r = (lane < 12) ? sb[lane] : 0.f;
#pragma unroll
        for (int o = 16; o; o >>= 1) r += __shfl_xor_sync(0xffffffffu, r, o);
        if (lane == 0) sb[12] = r;
    }
    __syncthreads();
    float mu = sb[12] * (1.0f / DIMV);
    float dx = xv.x - mu, dy = xv.y - mu;
    float vs = dx * dx + dy * dy;
    __syncthreads();
#pragma unroll
    for (int o = 16; o; o >>= 1) vs += __shfl_xor_sync(0xffffffffu, vs, o);
    if (lane == 0) sb[w] = vs;
    __syncthreads();
    if (w == 0) {
        float r = (lane < 12) ? sb[lane] : 0.f;
#pragma unroll
        for (int o = 16; o; o >>= 1) r += __shfl_xor_sync(0xffffffffu, r, o);
        if (lane == 0) sb[12] = r;
    }
    __syncthreads();
    float inv = rsqrtf(sb[12] * (1.0f / DIMV) + 1e-5f);
    int b = row >> 11;
    int i0 = 2 * tid;
    float v0 = dx * inv * g[i0] + be[i0];
    float v1 = dy * inv * g[i0 + 1] + be[i0 + 1];
    if (temb) { v0 += temb[b * DIMV + i0]; v1 += temb[b * DIMV + i0 + 1]; }
    float mx = fmaxf(fabsf(v0), fabsf(v1));
    __syncthreads();
#pragma unroll
    for (int o = 16; o; o >>= 1) mx = fmaxf(mx, __shfl_xor_sync(0xffffffffu, mx, o));
    if (lane == 0) sb[w] = mx;
    __syncthreads();
    if (w == 0) {
        float r = (lane < 12) ? sb[lane] : 0.f;
#pragma unroll
        for (int o = 16; o; o >>= 1) r = fmaxf(r, __shfl_xor_sync(0xffffffffu, r, o));
        if (lane == 0) sb[12] = r;
    }
    __syncthreads();
    float rmax = fmaxf(sb[12], 1e-20f);
    float invs = QMAX / rmax;
    char a1, a0, b1, b0;
    quant_limbs(v0, invs, a1, a0);
    quant_limbs(v1, invs, b1, b0);
    size_t oi = (size_t)row * DIMV + i0;
    *(char2*)(o1 + oi) = make_char2(a1, b1);
    *(char2*)(o0 + oi) = make_char2(a0, b0);
    if (tid == 0) sA[row] = rmax / QMAX;
}

// ---------------------------------------------------------------------------
// int8 limb GEMM (3-pass): C = sA sB^T * (16384 hh + 128 cx) + bias (+gelu)(+res)
// A planes [M][K], B planes [Nc][K]. Block 128x128, 512 thr (16 warps, 32x32
// warp tile), BK=64, 4-stage cp.async.
// ---------------------------------------------------------------------------
#define O_A1 0
#define O_A0 8192
#define O_B1 16384
#define O_B0 24576
#define STG_BYTES 32768
#define GEMM_SMEM (4 * STG_BYTES)   // 128KB

__device__ __forceinline__ void cp16s(uint32_t sdst, const void* src) {
    asm volatile("cp.async.cg.shared.global [%0], [%1], 16;" :: "r"(sdst), "l"(src));
}
#define LDSM4(r, addr)                                                        \
    asm volatile("ldmatrix.sync.aligned.m8n8.x4.shared.b16 {%0,%1,%2,%3}, [%4];" \
        : "=r"((r)[0]), "=r"((r)[1]), "=r"((r)[2]), "=r"((r)[3]) : "r"(addr))
#define MMA_S8(d, a, b0, b1)                                                  \
    asm volatile(                                                             \
        "mma.sync.aligned.m16n8k32.row.col.s32.s8.s8.s32 "                    \
        "{%0,%1,%2,%3},{%4,%5,%6,%7},{%8,%9},{%0,%1,%2,%3};"                  \
        : "+r"((d)[0]), "+r"((d)[1]), "+r"((d)[2]), "+r"((d)[3])              \
        : "r"((a)[0]), "r"((a)[1]), "r"((a)[2]), "r"((a)[3]), "r"(b0), "r"(b1))

__global__ void __launch_bounds__(512, 1) s8_gemm_kernel(
    const char* __restrict__ A1, const char* __restrict__ A0,
    const char* __restrict__ B1, const char* __restrict__ B0,
    const float* __restrict__ sA, const float* __restrict__ sB,
    const float* __restrict__ bias, const float* __restrict__ res,
    float* __restrict__ Cf, int Nc, int K, int act)
{
    extern __shared__ __align__(128) char smc[];
    const int tid = threadIdx.x;
    const int warp = tid >> 5, lane = tid & 31;
    const int wm = warp & 3, wn = warp >> 2;          // 4x4 warp grid, 32x32 tiles
    const int g = lane >> 2, t = lane & 3;
    const int bm = blockIdx.y * 128, bn = blockIdx.x * 128;
    const int nk = K >> 6;                            // BK=64

    uint32_t sbase;
    asm("{ .reg .u64 tt; cvta.to.shared.u64 tt, %1; cvt.u32.u64 %0, tt; }"
        : "=r"(sbase) : "l"(smc));

    // ldmatrix lane addressing (64B rows, 16B-chunk XOR swizzle)
    const int arl = lane & 15, aqb = lane >> 4;
    const int arsw = (arl >> 1) & 3;
    uint32_t aoff[2], aq[2];
#pragma unroll
    for (int mi = 0; mi < 2; mi++)
        aoff[mi] = (uint32_t)(wm * 32 + mi * 16 + arl) * 64u;
#pragma unroll
    for (int ks = 0; ks < 2; ks++)
        aq[ks] = (uint32_t)(((2 * ks + aqb) ^ arsw) << 4);
    const int nrl = (lane & 7) + ((lane >> 4) << 3);
    const int bqb = (lane >> 3) & 1;
    const int brsw = (nrl >> 1) & 3;
    uint32_t boff[2], bq[2];
#pragma unroll
    for (int ni = 0; ni < 2; ni++)
        boff[ni] = (uint32_t)(wn * 32 + ni * 16 + nrl) * 64u;
#pragma unroll
    for (int ks = 0; ks < 2; ks++)
        bq[ks] = (uint32_t)(((2 * ks + bqb) ^ brsw) << 4);

    int hh[2][2][2][4], cx[2][2][2][4];
#pragma unroll
    for (int mi = 0; mi < 2; mi++)
#pragma unroll
        for (int ni = 0; ni < 2; ni++)
#pragma unroll
            for (int pr = 0; pr < 2; pr++)
#pragma unroll
                for (int e = 0; e < 4; e++) { hh[mi][ni][pr][e] = 0; cx[mi][ni][pr][e] = 0; }

    // stage loader: 4 cp.async x 16B per thread (A 8KB/limb, B 8KB/limb)
    auto load_stage = [&](int buf, int it) {
        if (it < nk) {
            uint32_t st = sbase + buf * STG_BYTES;
            int kb = it * 64;
            int m = tid >> 2, q = tid & 3;
            uint32_t woff = (uint32_t)(m * 64 + ((q ^ ((m >> 1) & 3)) << 4));
            size_t ga = (size_t)(bm + m) * K + kb + q * 16;
            cp16s(st + O_A1 + woff, A1 + ga);
            cp16s(st + O_A0 + woff, A0 + ga);
            size_t gb = (size_t)(bn + m) * K + kb + q * 16;
            cp16s(st + O_B1 + woff, B1 + gb);
            cp16s(st + O_B0 + woff, B0 + gb);
        }
        asm volatile("cp.async.commit_group;");
    };

    load_stage(0, 0);
    load_stage(1, 1);
    load_stage(2, 2);

    for (int it = 0; it < nk; it++) {
        asm volatile("cp.async.wait_group 2;");
        __syncthreads();
        load_stage((it + 3) & 3, it + 3);

        uint32_t st = sbase + (it & 3) * STG_BYTES;
#pragma unroll
        for (int ks = 0; ks < 2; ks++) {
            uint32_t fA1[2][4], fA0[2][4], fB1[2][4], fB0[2][4];
#pragma unroll
            for (int mi = 0; mi < 2; mi++)
                LDSM4(fA1[mi], st + O_A1 + aoff[mi] + aq[ks]);
#pragma unroll
            for (int ni = 0; ni < 2; ni++)
                LDSM4(fB1[ni], st + O_B1 + boff[ni] + bq[ks]);
            // pass 1: q1 x q1
#pragma unroll
            for (int mi = 0; mi < 2; mi++)
#pragma unroll
                for (int ni = 0; ni < 2; ni++)
#pragma unroll
                    for (int pr = 0; pr < 2; pr++)
                        MMA_S8(hh[mi][ni][pr], fA1[mi], fB1[ni][2 * pr], fB1[ni][2 * pr + 1]);
            // pass 2: q1 x q0
#pragma unroll
            for (int ni = 0; ni < 2; ni++)
                LDSM4(fB0[ni], st + O_B0 + boff[ni] + bq[ks]);
#pragma unroll
            for (int mi = 0; mi < 2; mi++)
#pragma unroll
                for (int ni = 0; ni < 2; ni++)
#pragma unroll
                    for (int pr = 0; pr < 2; pr++)
                        MMA_S8(cx[mi][ni][pr], fA1[mi], fB0[ni][2 * pr], fB0[ni][2 * pr + 1]);
            // pass 3: q0 x q1
#pragma unroll
            for (int mi = 0; mi < 2; mi++)
                LDSM4(fA0[mi], st + O_A0 + aoff[mi] + aq[ks]);
#pragma unroll
            for (int mi = 0; mi < 2; mi++)
#pragma unroll
                for (int ni = 0; ni < 2; ni++)
#pragma unroll
                    for (int pr = 0; pr < 2; pr++)
                        MMA_S8(cx[mi][ni][pr], fA0[mi], fB1[ni][2 * pr], fB1[ni][2 * pr + 1]);
        }
    }

    // epilogue
#pragma unroll
    for (int mi = 0; mi < 2; mi++) {
#pragma unroll
        for (int ni = 0; ni < 2; ni++) {
#pragma unroll
            for (int pr = 0; pr < 2; pr++) {
                int col = bn + wn * 32 + ni * 16 + pr * 8 + 2 * t;
                float2 sb2 = *(const float2*)(sB + col);
                float2 bb = *(const float2*)(bias + col);
#pragma unroll
                for (int hf = 0; hf < 2; hf++) {
                    int r = bm + wm * 32 + mi * 16 + g + hf * 8;
                    float sa = sA[r];
                    float vx = sa * sb2.x * (16384.f * (float)hh[mi][ni][pr][2 * hf]
                              + 128.f * (float)cx[mi][ni][pr][2 * hf]) + bb.x;
                    float vy = sa * sb2.y * (16384.f * (float)hh[mi][ni][pr][2 * hf + 1]
                              + 128.f * (float)cx[mi][ni][pr][2 * hf + 1]) + bb.y;
                    if (act) { vx = gelu_f(vx); vy = gelu_f(vy); }
                    if (res) {
                        const float2 rr = *(const float2*)(res + (size_t)r * Nc + col);
                        vx += rr.x; vy += rr.y;
                    }
                    float2 o; o.x = vx; o.y = vy;
                    *(float2*)(Cf + (size_t)r * Nc + col) = o;
                }
            }
        }
    }
}

// ---------------------------------------------------------------------------
// ffn row quant: fp32 [row][3072] -> limb planes + scale
__global__ void __launch_bounds__(256) ffn_quant_kernel(const float* __restrict__ f,
    char* __restrict__ o1, char* __restrict__ o0, float* __restrict__ sA)
{
    __shared__ float sb[9];
    int row = blockIdx.x, tid = threadIdx.x;
    int lane = tid & 31, w = tid >> 5;
    const float4* base = (const float4*)(f + (size_t)row * DFF);
    float mx = 0.f;
#pragma unroll
    for (int i = 0; i < 3; i++) {
        float4 v = base[tid + i * 256];
        mx = fmaxf(mx, fmaxf(fmaxf(fabsf(v.x), fabsf(v.y)), fmaxf(fabsf(v.z), fabsf(v.w))));
    }
#pragma unroll
    for (int o = 16; o; o >>= 1) mx = fmaxf(mx, __shfl_xor_sync(0xffffffffu, mx, o));
    if (lane == 0) sb[w] = mx;
    __syncthreads();
    if (w == 0) {
        float r = (lane < 8) ? sb[lane] : 0.f;
#pragma unroll
        for (int o = 4; o; o >>= 1) r = fmaxf(r, __shfl_xor_sync(0xffffffffu, r, o));
        if (lane == 0) sb[8] = r;
    }
    __syncthreads();
    float rmax = fmaxf(sb[8], 1e-20f);
    float inv = QMAX / rmax;
    uint32_t* p1 = (uint32_t*)(o1 + (size_t)row * DFF);
    uint32_t* p0 = (uint32_t*)(o0 + (size_t)row * DFF);
#pragma unroll
    for (int i = 0; i < 3; i++) {
        float4 v = base[tid + i * 256];
        char a1, a0, b1, b0, c1, c0, d1, d0;
        quant_limbs(v.x, inv, a1, a0);
        quant_limbs(v.y, inv, b1, b0);
        quant_limbs(v.z, inv, c1, c0);
        quant_limbs(v.w, inv, d1, d0);
        p1[tid + i * 256] = (uint32_t)(uint8_t)a1 | ((uint32_t)(uint8_t)b1 << 8)
                          | ((uint32_t)(uint8_t)c1 << 16) | ((uint32_t)(uint8_t)d1 << 24);
        p0[tid + i * 256] = (uint32_t)(uint8_t)a0 | ((uint32_t)(uint8_t)b0 << 8)
                          | ((uint32_t)(uint8_t)c0 << 16) | ((uint32_t)(uint8_t)d0 << 24);
    }
    if (tid == 0) sA[row] = rmax / QMAX;
}

// ---------------------------------------------------------------------------
// Poincare distance + top-KNN per row
__global__ void __launch_bounds__(256) topk_kernel(const float* __restrict__ pos,
    const float* __restrict__ cptr, int* __restrict__ idxo, float* __restrict__ disto)
{
    __shared__ float arg[NTOK];
    __shared__ float rv[8];
    __shared__ int ri[8];
    int row = blockIdx.x;
    int b = row >> 11, i = row & (NTOK - 1);
    float c = cptr[0];
    float inv_sqc = rsqrtf(c);
    const float* pb = pos + (size_t)b * NTOK * 2;
    float yx = pb[i * 2], yy = pb[i * 2 + 1];
    float denY = 1.f - c * (yx * yx + yy * yy);
    for (int j = threadIdx.x; j < NTOK; j += 256) {
        float xx = pb[j * 2], xy = pb[j * 2 + 1];
        float dx = xx - yx, dy = xy - yy;
        float num = 2.f * c * (dx * dx + dy * dy);
        float den = (1.f - c * (xx * xx + xy * xy)) * denY;
        arg[j] = fmaxf(1.f + num / (den + 1e-8f), 1.f);
    }
    __syncthreads();
    int lane = threadIdx.x & 31, w = threadIdx.x >> 5;
    for (int sel = 0; sel < KNN; sel++) {
        float bv = 3.4e38f; int bi = 0x7fffffff;
        for (int j = threadIdx.x; j < NTOK; j += 256) {
            float a = arg[j];
            if (a < bv) { bv = a; bi = j; }
        }
#pragma unroll
        for (int o = 16; o; o >>= 1) {
            float ov = __shfl_xor_sync(0xffffffffu, bv, o);
            int   oi = __shfl_xor_sync(0xffffffffu, bi, o);
            if (ov < bv || (ov == bv && oi < bi)) { bv = ov; bi = oi; }
        }
        if (lane == 0) { rv[w] = bv; ri[w] = bi; }
        __syncthreads();
        if (threadIdx.x == 0) {
            float fv = rv[0]; int fi = ri[0];
            for (int t2 = 1; t2 < 8; t2++)
                if (rv[t2] < fv || (rv[t2] == fv && ri[t2] < fi)) { fv = rv[t2]; fi = ri[t2]; }
            idxo[(size_t)row * KNN + sel] = fi;
            disto[(size_t)row * KNN + sel] = acoshf(fv) * inv_sqc;
            arg[fi] = 3.4e38f;
        }
        __syncthreads();
    }
}

// ---------------------------------------------------------------------------
// kNN attention over fused qkv [row][2304]; int8-limb output + row scale
__global__ void __launch_bounds__(384) attn_quant_kernel(const float* __restrict__ qkv,
    const int* __restrict__ idx, const float* __restrict__ dist,
    const float* __restrict__ log_tau,
    char* __restrict__ o1, char* __restrict__ o0, float* __restrict__ sA)
{
    __shared__ int sidx[KNN];
    __shared__ float sgeo[KNN];
    __shared__ float smax[13];
    int row = blockIdx.x;
    int lane = threadIdx.x & 31, h = threadIdx.x >> 5;
    float invtau = 1.f / (expf(log_tau[0]) + 1e-8f);
    if (threadIdx.x < KNN) {
        sidx[threadIdx.x] = idx[(size_t)row * KNN + threadIdx.x];
        sgeo[threadIdx.x] = -dist[(size_t)row * KNN + threadIdx.x] * invtau;
    }
    __syncthreads();
    int b = row >> 11;
    const float* qp = qkv + (size_t)row * 2304 + h * HDIM;
    float q0 = qp[2 * lane], q1 = qp[2 * lane + 1];
    const float* kb = qkv + (size_t)b * NTOK * 2304 + 768 + h * HDIM;
    const float* vb = qkv + (size_t)b * NTOK * 2304 + 1536 + h * HDIM;
    float myscore = 0.f;
#pragma unroll 4
    for (int j = 0; j < KNN; j++) {
        const float* kp = kb + (size_t)sidx[j] * 2304;
        float p = q0 * kp[2 * lane] + q1 * kp[2 * lane + 1];
#pragma unroll
        for (int o = 16; o; o >>= 1) p += __shfl_xor_sync(0xffffffffu, p, o);
        if (lane == j) myscore = p * 0.125f + sgeo[j];
    }
    float m = myscore;
#pragma unroll
    for (int o = 16; o; o >>= 1) m = fmaxf(m, __shfl_xor_sync(0xffffffffu, m, o));
    float e = expf(myscore - m);
    float s = e;
#pragma unroll
    for (int o = 16; o; o >>= 1) s += __shfl_xor_sync(0xffffffffu, s, o);
    float p = e / s;
    float v0 = 0.f, v1 = 0.f;
#pragma unroll 4
    for (int j = 0; j < KNN; j++) {
        float pj = __shfl_sync(0xffffffffu, p, j);
        const float* vp = vb + (size_t)sidx[j] * 2304;
        v0 += pj * vp[2 * lane]; v1 += pj * vp[2 * lane + 1];
    }
    float mx = fmaxf(fabsf(v0), fabsf(v1));
#pragma unroll
    for (int o = 16; o; o >>= 1) mx = fmaxf(mx, __shfl_xor_sync(0xffffffffu, mx, o));
    if (lane == 0) smax[h] = mx;
    __syncthreads();
    if (h == 0) {
        float r = (lane < 12) ? smax[lane] : 0.f;
#pragma unroll
        for (int o = 16; o; o >>= 1) r = fmaxf(r, __shfl_xor_sync(0xffffffffu, r, o));
        if (lane == 0) smax[12] = r;
    }
    __syncthreads();
    float rmax = fmaxf(smax[12], 1e-20f);
    float inv = QMAX / rmax;
    char a1, a0, b1c, b0c;
    quant_limbs(v0, inv, a1, a0);
    quant_limbs(v1, inv, b1c, b0c);
    size_t oi = (size_t)row * DIMV + h * HDIM + 2 * lane;
    *(char2*)(o1 + oi) = make_char2(a1, b1c);
    *(char2*)(o0 + oi) = make_char2(a0, b0c);
    if (threadIdx.x == 0) sA[row] = rmax / QMAX;
}

// ---------------------------------------------------------------------------
extern "C" void kernel_launch(void* const* d_in, const int* in_sizes, int n_in,
                              void* d_out, int out_size)
{
    const float* x    = (const float*)d_in[0];
    const float* pos  = (const float*)d_in[1];
    const float* c    = (const float*)d_in[2];
    const float* temb = (const float*)d_in[3];
    const float* Wq = (const float*)d_in[4],  *bq = (const float*)d_in[5];
    const float* Wk = (const float*)d_in[6],  *bk = (const float*)d_in[7];
    const float* Wv = (const float*)d_in[8],  *bv = (const float*)d_in[9];
    const float* Wo = (const float*)d_in[10], *bo = (const float*)d_in[11];
    const float* W1 = (const float*)d_in[12], *b1 = (const float*)d_in[13];
    const float* W2 = (const float*)d_in[14], *b2 = (const float*)d_in[15];
    const float* g1 = (const float*)d_in[16], *be1 = (const float*)d_in[17];
    const float* g2 = (const float*)d_in[18], *be2 = (const float*)d_in[19];
    const float* log_tau = (const float*)d_in[20];
    float* out = (float*)d_out;

    char* arena; cudaGetSymbolAddress((void**)&arena, g_arena);
    int* idxp;   cudaGetSymbolAddress((void**)&idxp, g_idx);
    float* distp;cudaGetSymbolAddress((void**)&distp, g_dist);

    char* p = arena;
    auto carve = [&](size_t bytes) { char* r = p; p += (bytes + 127) & ~(size_t)127; return r; };
    char* h1   = carve((size_t)MROWS * 768);
    char* h0   = carve((size_t)MROWS * 768);
    char* att1 = carve((size_t)MROWS * 768);
    char* att0 = carve((size_t)MROWS * 768);
    char* h21  = carve((size_t)MROWS * 768);
    char* h20  = carve((size_t)MROWS * 768);
    char* ffn1 = carve((size_t)MROWS * 3072);
    char* ffn0 = carve((size_t)MROWS * 3072);
    char* wqkv1 = carve((size_t)2304 * 768);
    char* wqkv0 = carve((size_t)2304 * 768);
    char* wo1  = carve((size_t)768 * 768);
    char* wo0  = carve((size_t)768 * 768);
    char* w11  = carve((size_t)3072 * 768);
    char* w10  = carve((size_t)3072 * 768);
    char* w21  = carve((size_t)768 * 3072);
    char* w20  = carve((size_t)768 * 3072);
    float* qkv   = (float*)carve((size_t)MROWS * 2304 * 4);
    float* x2    = (float*)carve((size_t)MROWS * 768 * 4);
    float* ffn_f = (float*)carve((size_t)MROWS * 3072 * 4);
    float* partial = (float*)carve(8 * PSTRIDE * 4);
    float* sAh   = (float*)carve(MROWS * 4);
    float* sAatt = (float*)carve(MROWS * 4);
    float* sAh2  = (float*)carve(MROWS * 4);
    float* sAffn = (float*)carve(MROWS * 4);
    float* sBqkv = (float*)carve(2304 * 4);
    float* sBo   = (float*)carve(768 * 4);
    float* sB1   = (float*)carve(3072 * 4);
    float* sB2   = (float*)carve(768 * 4);
    float* bqkv  = (float*)carve(2304 * 4);

    cudaFuncSetAttribute(s8_gemm_kernel,
                         cudaFuncAttributeMaxDynamicSharedMemorySize, GEMM_SMEM);

    // launches 1-3, then QKV GEMM as launch 4 (= ncu capture slot)
    ln_quant_kernel<<<MROWS, 384>>>(x, g1, be1, temb, h1, h0, sAh);
    wpmax_qkv_kernel<<<dim3(9, 8), 256>>>(Wq, Wk, Wv, bq, bk, bv, partial, bqkv);
    wquantT3_kernel<<<dim3(24, 24, 3), 256>>>(Wq, Wk, Wv, partial, sBqkv, wqkv1, wqkv0);
    s8_gemm_kernel<<<dim3(18, 32), 512, GEMM_SMEM>>>(h1, h0, wqkv1, wqkv0,
        sAh, sBqkv, bqkv, nullptr, qkv, 2304, 768, 0);

    topk_kernel<<<MROWS, 256>>>(pos, c, idxp, distp);
    attn_quant_kernel<<<MROWS, 384>>>(qkv, idxp, distp, log_tau, att1, att0, sAatt);

    wpmax_rest_kernel<<<dim3(18, 8), 256>>>(Wo, W1, W2, partial);
    wquantT_kernel<<<dim3(24, 24), 256>>>(Wo, partial, 2304, sBo, wo1, wo0, 768, 768);
    wquantT_kernel<<<dim3(96, 24), 256>>>(W1, partial, 3072, sB1, w11, w10, 3072, 768);
    wquantT_kernel<<<dim3(24, 96), 256>>>(W2, partial, 6144, sB2, w21, w20, 768, 3072);

    // x2 = x + att @ Wo
    s8_gemm_kernel<<<dim3(6, 32), 512, GEMM_SMEM>>>(att1, att0, wo1, wo0,
        sAatt, sBo, bo, x, x2, 768, 768, 0);
    ln_quant_kernel<<<MROWS, 384>>>(x2, g2, be2, nullptr, h21, h20, sAh2);

    // ffn_f = gelu(h2 @ W1)
    s8_gemm_kernel<<<dim3(24, 32), 512, GEMM_SMEM>>>(h21, h20, w11, w10,
        sAh2, sB1, b1, nullptr, ffn_f, 3072, 768, 1);
    ffn_quant_kernel<<<MROWS, 256>>>(ffn_f, ffn1, ffn0, sAffn);

    // out = x2 + ffn @ W2
    s8_gemm_kernel<<<dim3(6, 32), 512, GEMM_SMEM>>>(ffn1, ffn0, w21, w20,
        sAffn, sB2, b2, x2, out, 768, 3072, 0);
}

// round 9
// speedup vs baseline: 1.5219x; 1.0720x over previous
#include <cuda_runtime.h>
#include <cuda_bf16.h>
#include <math.h>
#include <stdint.h>

#define NTOK 2048
#define BATCH 2
#define DIMV 768
#define NHEAD 12
#define HDIM 64
#define KNN 32
#define DFF 3072
#define MROWS 4096   // BATCH*NTOK
#define QMAX 16256.0f
#define PSTRIDE 8192

// ---------------------------------------------------------------------------
#define ARENA_BYTES 172000000ull
__device__ __align__(128) char g_arena[ARENA_BYTES];
__device__ int   g_idx[MROWS * KNN];
__device__ float g_dist[MROWS * KNN];

// ---------------------------------------------------------------------------
__device__ __forceinline__ float gelu_f(float v) {
    return 0.5f * v * (1.f + erff(v * 0.70710678118654752f));
}
__device__ __forceinline__ void quant_limbs(float v, float inv_s, char& q1c, char& q0c) {
    int q = __float2int_rn(v * inv_s);
    q = max(-16256, min(16256, q));
    int q1 = (q + 64) >> 7;
    int q0 = q - (q1 << 7);
    q1c = (char)q1; q0c = (char)q0;
}

// ---------------------------------------------------------------------------
// parallel per-column absmax, 8 K-chunks; qkv variant also concats bias
__global__ void __launch_bounds__(256) wpmax_qkv_kernel(
    const float* __restrict__ Wq, const float* __restrict__ Wk, const float* __restrict__ Wv,
    const float* __restrict__ bq, const float* __restrict__ bk, const float* __restrict__ bv,
    float* __restrict__ partial, float* __restrict__ bqkv)
{
    int col = blockIdx.x * 256 + threadIdx.x;        // 0..2303
    int w = col / 768, c = col - w * 768;
    const float* W = (w == 0) ? Wq : (w == 1) ? Wk : Wv;
    int k0 = blockIdx.y * 96;
    float mx = 0.f;
#pragma unroll 8
    for (int k = k0; k < k0 + 96; k++) mx = fmaxf(mx, fabsf(W[(size_t)k * 768 + c]));
    partial[blockIdx.y * PSTRIDE + col] = mx;
    if (blockIdx.y == 0)
        bqkv[col] = ((w == 0) ? bq : (w == 1) ? bk : bv)[c];
}

__global__ void __launch_bounds__(256) wpmax_rest_kernel(
    const float* __restrict__ Wo, const float* __restrict__ W1, const float* __restrict__ W2,
    float* __restrict__ partial)
{
    int j = blockIdx.x * 256 + threadIdx.x;          // 0..4607
    const float* W; int c, K, Nc;
    if (j < 768)       { W = Wo; c = j;        K = 768;  Nc = 768;  }
    else if (j < 3840) { W = W1; c = j - 768;  K = 768;  Nc = 3072; }
    else               { W = W2; c = j - 3840; K = 3072; Nc = 768;  }
    int chunk = K >> 3;
    int k0 = blockIdx.y * chunk;
    float mx = 0.f;
#pragma unroll 8
    for (int k = k0; k < k0 + chunk; k++) mx = fmaxf(mx, fabsf(W[(size_t)k * Nc + c]));
    partial[blockIdx.y * PSTRIDE + 2304 + j] = mx;
}

// transpose+quantize tile; reduces partial->scale inline, writes sB
__device__ __forceinline__ void wq_tile(const float* W, const float* partial,
    int pcolOff, float* sBout, char* o1, char* o0, int Nc, int Kd, int rowOff,
    int n0, int k0, int tid)
{
    __shared__ char s1[32][33], s0[32][33];
    int tx = tid & 31, tyg = tid >> 5;
    int n = n0 + tx;
    float mx = 0.f;
#pragma unroll
    for (int j = 0; j < 8; j++) mx = fmaxf(mx, partial[j * PSTRIDE + pcolOff + n]);
    mx = fmaxf(mx, 1e-20f);
    float inv = QMAX / mx;
    if (k0 == 0 && tyg == 0) sBout[rowOff + n] = mx / QMAX;
#pragma unroll
    for (int j = 0; j < 4; j++) {
        int kl = tyg * 4 + j;
        float v = W[(size_t)(k0 + kl) * Nc + n];
        quant_limbs(v, inv, s1[kl][tx], s0[kl][tx]);
    }
    __syncthreads();
#pragma unroll
    for (int j = 0; j < 4; j++) {
        int nl = tyg * 4 + j;
        size_t oidx = (size_t)(rowOff + n0 + nl) * Kd + k0 + tx;
        o1[oidx] = s1[tx][nl];
        o0[oidx] = s0[tx][nl];
    }
}

__global__ void __launch_bounds__(256) wquantT3_kernel(
    const float* __restrict__ Wq, const float* __restrict__ Wk, const float* __restrict__ Wv,
    const float* __restrict__ partial, float* __restrict__ sB,
    char* __restrict__ o1, char* __restrict__ o0)
{
    int z = blockIdx.z;
    const float* W = (z == 0) ? Wq : (z == 1) ? Wk : Wv;
    wq_tile(W, partial, z * 768, sB, o1, o0, 768, 768, z * 768,
            blockIdx.x * 32, blockIdx.y * 32, threadIdx.x);
}

__global__ void __launch_bounds__(256) wquantT_kernel(
    const float* __restrict__ W, const float* __restrict__ partial, int pcolOff,
    float* __restrict__ sB, char* __restrict__ o1, char* __restrict__ o0, int Nc, int Kd)
{
    wq_tile(W, partial, pcolOff, sB, o1, o0, Nc, Kd, 0,
            blockIdx.x * 32, blockIdx.y * 32, threadIdx.x);
}

// ---------------------------------------------------------------------------
// LayerNorm (+time emb) -> int8 limb planes + per-row scale
__global__ void __launch_bounds__(384) ln_quant_kernel(const float* __restrict__ x,
    const float* __restrict__ g, const float* __restrict__ be,
    const float* __restrict__ temb, char* __restrict__ o1, char* __restrict__ o0,
    float* __restrict__ sA)
{
    __shared__ float sb[13];
    int row = blockIdx.x, tid = threadIdx.x;
    int lane = tid & 31, w = tid >> 5;
    float2 xv = *(const float2*)(x + (size_t)row * DIMV + 2 * tid);
    float s = xv.x + xv.y;
#pragma unroll
    for (int o = 16; o; o >>= 1) s += __shfl_xor_sync(0xffffffffu, s, o);
    if (lane == 0) sb[w] = s;
    __syncthreads();
    if (w == 0) {
        float r = (lane < 12) ? sb[lane] : 0.f;
#pragma unroll
        for (int o = 16; o; o >>= 1) r += __shfl_xor_sync(0xffffffffu, r, o);
        if (lane == 0) sb[12] = r;
    }
    __syncthreads();
    float mu = sb[12] * (1.0f / DIMV);
    float dx = xv.x - mu, dy = xv.y - mu;
    float vs = dx * dx + dy * dy;
    __syncthreads();
#pragma unroll
    for (int o = 16; o; o >>= 1) vs += __shfl_xor_sync(0xffffffffu, vs, o);
    if (lane == 0) sb[w] = vs;
    __syncthreads();
    if (w == 0) {
        float r = (lane < 12) ? sb[lane] : 0.f;
#pragma unroll
        for (int o = 16; o; o >>= 1) r += __shfl_xor_sync(0xffffffffu, r, o);
        if (lane == 0) sb[12] = r;
    }
    __syncthreads();
    float inv = rsqrtf(sb[12] * (1.0f / DIMV) + 1e-5f);
    int b = row >> 11;
    int i0 = 2 * tid;
    float v0 = dx * inv * g[i0] + be[i0];
    float v1 = dy * inv * g[i0 + 1] + be[i0 + 1];
    if (temb) { v0 += temb[b * DIMV + i0]; v1 += temb[b * DIMV + i0 + 1]; }
    float mx = fmaxf(fabsf(v0), fabsf(v1));
    __syncthreads();
#pragma unroll
    for (int o = 16; o; o >>= 1) mx = fmaxf(mx, __shfl_xor_sync(0xffffffffu, mx, o));
    if (lane == 0) sb[w] = mx;
    __syncthreads();
    if (w == 0) {
        float r = (lane < 12) ? sb[lane] : 0.f;
#pragma unroll
        for (int o = 16; o; o >>= 1) r = fmaxf(r, __shfl_xor_sync(0xffffffffu, r, o));
        if (lane == 0) sb[12] = r;
    }
    __syncthreads();
    float rmax = fmaxf(sb[12], 1e-20f);
    float invs = QMAX / rmax;
    char a1, a0, b1, b0;
    quant_limbs(v0, invs, a1, a0);
    quant_limbs(v1, invs, b1, b0);
    size_t oi = (size_t)row * DIMV + i0;
    *(char2*)(o1 + oi) = make_char2(a1, b1);
    *(char2*)(o0 + oi) = make_char2(a0, b0);
    if (tid == 0) sA[row] = rmax / QMAX;
}

// ---------------------------------------------------------------------------
// int8 limb GEMM (3-pass). Block 128x128, 512 thr, BK=64, 4-stage cp.async.
// ---------------------------------------------------------------------------
#define O_A1 0
#define O_A0 8192
#define O_B1 16384
#define O_B0 24576
#define STG_BYTES 32768
#define GEMM_SMEM (4 * STG_BYTES)   // 128KB

__device__ __forceinline__ void cp16s(uint32_t sdst, const void* src) {
    asm volatile("cp.async.cg.shared.global [%0], [%1], 16;" :: "r"(sdst), "l"(src));
}
#define LDSM4(r, addr)                                                        \
    asm volatile("ldmatrix.sync.aligned.m8n8.x4.shared.b16 {%0,%1,%2,%3}, [%4];" \
        : "=r"((r)[0]), "=r"((r)[1]), "=r"((r)[2]), "=r"((r)[3]) : "r"(addr))
#define MMA_S8(d, a, b0, b1)                                                  \
    asm volatile(                                                             \
        "mma.sync.aligned.m16n8k32.row.col.s32.s8.s8.s32 "                    \
        "{%0,%1,%2,%3},{%4,%5,%6,%7},{%8,%9},{%0,%1,%2,%3};"                  \
        : "+r"((d)[0]), "+r"((d)[1]), "+r"((d)[2]), "+r"((d)[3])              \
        : "r"((a)[0]), "r"((a)[1]), "r"((a)[2]), "r"((a)[3]), "r"(b0), "r"(b1))

__global__ void __launch_bounds__(512, 1) s8_gemm_kernel(
    const char* __restrict__ A1, const char* __restrict__ A0,
    const char* __restrict__ B1, const char* __restrict__ B0,
    const float* __restrict__ sA, const float* __restrict__ sB,
    const float* __restrict__ bias, const float* __restrict__ res,
    float* __restrict__ Cf, int Nc, int K, int act)
{
    extern __shared__ __align__(128) char smc[];
    const int tid = threadIdx.x;
    const int warp = tid >> 5, lane = tid & 31;
    const int wm = warp & 3, wn = warp >> 2;
    const int g = lane >> 2, t = lane & 3;
    const int bm = blockIdx.y * 128, bn = blockIdx.x * 128;
    const int nk = K >> 6;

    uint32_t sbase;
    asm("{ .reg .u64 tt; cvta.to.shared.u64 tt, %1; cvt.u32.u64 %0, tt; }"
        : "=r"(sbase) : "l"(smc));

    const int arl = lane & 15, aqb = lane >> 4;
    const int arsw = (arl >> 1) & 3;
    uint32_t aoff[2], aq[2];
#pragma unroll
    for (int mi = 0; mi < 2; mi++)
        aoff[mi] = (uint32_t)(wm * 32 + mi * 16 + arl) * 64u;
#pragma unroll
    for (int ks = 0; ks < 2; ks++)
        aq[ks] = (uint32_t)(((2 * ks + aqb) ^ arsw) << 4);
    const int nrl = (lane & 7) + ((lane >> 4) << 3);
    const int bqb = (lane >> 3) & 1;
    const int brsw = (nrl >> 1) & 3;
    uint32_t boff[2], bq[2];
#pragma unroll
    for (int ni = 0; ni < 2; ni++)
        boff[ni] = (uint32_t)(wn * 32 + ni * 16 + nrl) * 64u;
#pragma unroll
    for (int ks = 0; ks < 2; ks++)
        bq[ks] = (uint32_t)(((2 * ks + bqb) ^ brsw) << 4);

    int hh[2][2][2][4], cx[2][2][2][4];
#pragma unroll
    for (int mi = 0; mi < 2; mi++)
#pragma unroll
        for (int ni = 0; ni < 2; ni++)
#pragma unroll
            for (int pr = 0; pr < 2; pr++)
#pragma unroll
                for (int e = 0; e < 4; e++) { hh[mi][ni][pr][e] = 0; cx[mi][ni][pr][e] = 0; }

    auto load_stage = [&](int buf, int it) {
        if (it < nk) {
            uint32_t st = sbase + buf * STG_BYTES;
            int kb = it * 64;
            int m = tid >> 2, q = tid & 3;
            uint32_t woff = (uint32_t)(m * 64 + ((q ^ ((m >> 1) & 3)) << 4));
            size_t ga = (size_t)(bm + m) * K + kb + q * 16;
            cp16s(st + O_A1 + woff, A1 + ga);
            cp16s(st + O_A0 + woff, A0 + ga);
            size_t gb = (size_t)(bn + m) * K + kb + q * 16;
            cp16s(st + O_B1 + woff, B1 + gb);
            cp16s(st + O_B0 + woff, B0 + gb);
        }
        asm volatile("cp.async.commit_group;");
    };

    load_stage(0, 0);
    load_stage(1, 1);
    load_stage(2, 2);

    for (int it = 0; it < nk; it++) {
        asm volatile("cp.async.wait_group 2;");
        __syncthreads();
        load_stage((it + 3) & 3, it + 3);

        uint32_t st = sbase + (it & 3) * STG_BYTES;
#pragma unroll
        for (int ks = 0; ks < 2; ks++) {
            uint32_t fA1[2][4], fA0[2][4], fB1[2][4], fB0[2][4];
#pragma unroll
            for (int mi = 0; mi < 2; mi++)
                LDSM4(fA1[mi], st + O_A1 + aoff[mi] + aq[ks]);
#pragma unroll
            for (int ni = 0; ni < 2; ni++)
                LDSM4(fB1[ni], st + O_B1 + boff[ni] + bq[ks]);
#pragma unroll
            for (int mi = 0; mi < 2; mi++)
#pragma unroll
                for (int ni = 0; ni < 2; ni++)
#pragma unroll
                    for (int pr = 0; pr < 2; pr++)
                        MMA_S8(hh[mi][ni][pr], fA1[mi], fB1[ni][2 * pr], fB1[ni][2 * pr + 1]);
#pragma unroll
            for (int ni = 0; ni < 2; ni++)
                LDSM4(fB0[ni], st + O_B0 + boff[ni] + bq[ks]);
#pragma unroll
            for (int mi = 0; mi < 2; mi++)
#pragma unroll
                for (int ni = 0; ni < 2; ni++)
#pragma unroll
                    for (int pr = 0; pr < 2; pr++)
                        MMA_S8(cx[mi][ni][pr], fA1[mi], fB0[ni][2 * pr], fB0[ni][2 * pr + 1]);
#pragma unroll
            for (int mi = 0; mi < 2; mi++)
                LDSM4(fA0[mi], st + O_A0 + aoff[mi] + aq[ks]);
#pragma unroll
            for (int mi = 0; mi < 2; mi++)
#pragma unroll
                for (int ni = 0; ni < 2; ni++)
#pragma unroll
                    for (int pr = 0; pr < 2; pr++)
                        MMA_S8(cx[mi][ni][pr], fA0[mi], fB1[ni][2 * pr], fB1[ni][2 * pr + 1]);
        }
    }

#pragma unroll
    for (int mi = 0; mi < 2; mi++) {
#pragma unroll
        for (int ni = 0; ni < 2; ni++) {
#pragma unroll
            for (int pr = 0; pr < 2; pr++) {
                int col = bn + wn * 32 + ni * 16 + pr * 8 + 2 * t;
                float2 sb2 = *(const float2*)(sB + col);
                float2 bb = *(const float2*)(bias + col);
#pragma unroll
                for (int hf = 0; hf < 2; hf++) {
                    int r = bm + wm * 32 + mi * 16 + g + hf * 8;
                    float sa = sA[r];
                    float vx = sa * sb2.x * (16384.f * (float)hh[mi][ni][pr][2 * hf]
                              + 128.f * (float)cx[mi][ni][pr][2 * hf]) + bb.x;
                    float vy = sa * sb2.y * (16384.f * (float)hh[mi][ni][pr][2 * hf + 1]
                              + 128.f * (float)cx[mi][ni][pr][2 * hf + 1]) + bb.y;
                    if (act) { vx = gelu_f(vx); vy = gelu_f(vy); }
                    if (res) {
                        const float2 rr = *(const float2*)(res + (size_t)r * Nc + col);
                        vx += rr.x; vy += rr.y;
                    }
                    float2 o; o.x = vx; o.y = vy;
                    *(float2*)(Cf + (size_t)r * Nc + col) = o;
                }
            }
        }
    }
}

// ---------------------------------------------------------------------------
// ffn row quant
__global__ void __launch_bounds__(256) ffn_quant_kernel(const float* __restrict__ f,
    char* __restrict__ o1, char* __restrict__ o0, float* __restrict__ sA)
{
    __shared__ float sb[9];
    int row = blockIdx.x, tid = threadIdx.x;
    int lane = tid & 31, w = tid >> 5;
    const float4* base = (const float4*)(f + (size_t)row * DFF);
    float mx = 0.f;
#pragma unroll
    for (int i = 0; i < 3; i++) {
        float4 v = base[tid + i * 256];
        mx = fmaxf(mx, fmaxf(fmaxf(fabsf(v.x), fabsf(v.y)), fmaxf(fabsf(v.z), fabsf(v.w))));
    }
#pragma unroll
    for (int o = 16; o; o >>= 1) mx = fmaxf(mx, __shfl_xor_sync(0xffffffffu, mx, o));
    if (lane == 0) sb[w] = mx;
    __syncthreads();
    if (w == 0) {
        float r = (lane < 8) ? sb[lane] : 0.f;
#pragma unroll
        for (int o = 4; o; o >>= 1) r = fmaxf(r, __shfl_xor_sync(0xffffffffu, r, o));
        if (lane == 0) sb[8] = r;
    }
    __syncthreads();
    float rmax = fmaxf(sb[8], 1e-20f);
    float inv = QMAX / rmax;
    uint32_t* p1 = (uint32_t*)(o1 + (size_t)row * DFF);
    uint32_t* p0 = (uint32_t*)(o0 + (size_t)row * DFF);
#pragma unroll
    for (int i = 0; i < 3; i++) {
        float4 v = base[tid + i * 256];
        char a1, a0, b1, b0, c1, c0, d1, d0;
        quant_limbs(v.x, inv, a1, a0);
        quant_limbs(v.y, inv, b1, b0);
        quant_limbs(v.z, inv, c1, c0);
        quant_limbs(v.w, inv, d1, d0);
        p1[tid + i * 256] = (uint32_t)(uint8_t)a1 | ((uint32_t)(uint8_t)b1 << 8)
                          | ((uint32_t)(uint8_t)c1 << 16) | ((uint32_t)(uint8_t)d1 << 24);
        p0[tid + i * 256] = (uint32_t)(uint8_t)a0 | ((uint32_t)(uint8_t)b0 << 8)
                          | ((uint32_t)(uint8_t)c0 << 16) | ((uint32_t)(uint8_t)d0 << 24);
    }
    if (tid == 0) sA[row] = rmax / QMAX;
}

// ---------------------------------------------------------------------------
// Poincare top-KNN: sorted-run merge selection.
// Each thread sorts its 8 (val,idx) pairs (Batcher network), then 32 rounds of
// argmin over 256 run-heads. (val,idx) lexicographic order == old behavior.
// ---------------------------------------------------------------------------
__device__ __forceinline__ void ce_pair(float& v0, int& i0, float& v1, int& i1) {
    bool sw = (v1 < v0) || (v1 == v0 && i1 < i0);
    float tv = sw ? v1 : v0; float uv = sw ? v0 : v1;
    int   ti = sw ? i1 : i0; int   ui = sw ? i0 : i1;
    v0 = tv; i0 = ti; v1 = uv; i1 = ui;
}

__global__ void __launch_bounds__(256) topk_kernel(const float* __restrict__ pos,
    const float* __restrict__ cptr, int* __restrict__ idxo, float* __restrict__ disto)
{
    __shared__ float sv[NTOK];
    __shared__ int   si[NTOK];
    __shared__ float wv[8]; __shared__ int wi[8]; __shared__ int wt[8];
    __shared__ float selv[KNN]; __shared__ int seli[KNN];
    __shared__ int swin;
    int row = blockIdx.x, tid = threadIdx.x;
    int b = row >> 11, i = row & (NTOK - 1);
    float c = cptr[0];
    float inv_sqc = rsqrtf(c);
    const float* pb = pos + (size_t)b * NTOK * 2;
    float yx = pb[i * 2], yy = pb[i * 2 + 1];
    float denY = 1.f - c * (yx * yx + yy * yy);

    // compute 8 args per thread
    float v[8]; int ix[8];
#pragma unroll
    for (int u = 0; u < 8; u++) {
        int j = tid + u * 256;
        float2 pj = *(const float2*)(pb + j * 2);
        float dx = pj.x - yx, dy = pj.y - yy;
        float num = 2.f * c * (dx * dx + dy * dy);
        float den = (1.f - c * (pj.x * pj.x + pj.y * pj.y)) * denY;
        v[u] = fmaxf(1.f + num / (den + 1e-8f), 1.f);
        ix[u] = j;
    }
    // Batcher odd-even mergesort for 8 elements (19 CE)
    ce_pair(v[0],ix[0],v[1],ix[1]); ce_pair(v[2],ix[2],v[3],ix[3]);
    ce_pair(v[4],ix[4],v[5],ix[5]); ce_pair(v[6],ix[6],v[7],ix[7]);
    ce_pair(v[0],ix[0],v[2],ix[2]); ce_pair(v[1],ix[1],v[3],ix[3]);
    ce_pair(v[4],ix[4],v[6],ix[6]); ce_pair(v[5],ix[5],v[7],ix[7]);
    ce_pair(v[1],ix[1],v[2],ix[2]); ce_pair(v[5],ix[5],v[6],ix[6]);
    ce_pair(v[0],ix[0],v[4],ix[4]); ce_pair(v[1],ix[1],v[5],ix[5]);
    ce_pair(v[2],ix[2],v[6],ix[6]); ce_pair(v[3],ix[3],v[7],ix[7]);
    ce_pair(v[2],ix[2],v[4],ix[4]); ce_pair(v[3],ix[3],v[5],ix[5]);
    ce_pair(v[1],ix[1],v[2],ix[2]); ce_pair(v[3],ix[3],v[4],ix[4]);
    ce_pair(v[5],ix[5],v[6],ix[6]);
#pragma unroll
    for (int u = 0; u < 8; u++) { sv[tid * 8 + u] = v[u]; si[tid * 8 + u] = ix[u]; }
    __syncthreads();

    int lane = tid & 31, w = tid >> 5;
    int ptr = 0;
    float hv = v[0]; int hi = ix[0];   // head cached (ptr=0)
    for (int sel = 0; sel < KNN; sel++) {
        float bv = hv; int bi = hi; int bt = tid;
#pragma unroll
        for (int o = 16; o; o >>= 1) {
            float ov = __shfl_xor_sync(0xffffffffu, bv, o);
            int   oi = __shfl_xor_sync(0xffffffffu, bi, o);
            int   ot = __shfl_xor_sync(0xffffffffu, bt, o);
            if (ov < bv || (ov == bv && oi < bi)) { bv = ov; bi = oi; bt = ot; }
        }
        if (lane == 0) { wv[w] = bv; wi[w] = bi; wt[w] = bt; }
        __syncthreads();
        if (tid == 0) {
            float fv = wv[0]; int fi = wi[0]; int ft = wt[0];
#pragma unroll
            for (int t2 = 1; t2 < 8; t2++)
                if (wv[t2] < fv || (wv[t2] == fv && wi[t2] < fi)) {
                    fv = wv[t2]; fi = wi[t2]; ft = wt[t2];
                }
            selv[sel] = fv; seli[sel] = fi; swin = ft;
        }
        __syncthreads();
        if (tid == swin) {
            ptr++;
            if (ptr < 8) { hv = sv[tid * 8 + ptr]; hi = si[tid * 8 + ptr]; }
            else         { hv = 3.4e38f; hi = 0x7fffffff; }
        }
    }
    __syncthreads();
    if (tid < KNN) {
        idxo[(size_t)row * KNN + tid] = seli[tid];
        disto[(size_t)row * KNN + tid] = acoshf(selv[tid]) * inv_sqc;
    }
}

// ---------------------------------------------------------------------------
// kNN attention: batched gather loads (MLP 16), int8-limb output + row scale
__global__ void __launch_bounds__(384) attn_quant_kernel(const float* __restrict__ qkv,
    const int* __restrict__ idx, const float* __restrict__ dist,
    const float* __restrict__ log_tau,
    char* __restrict__ o1, char* __restrict__ o0, float* __restrict__ sA)
{
    __shared__ int sidx[KNN];
    __shared__ float sgeo[KNN];
    __shared__ float smax[13];
    int row = blockIdx.x;
    int lane = threadIdx.x & 31, h = threadIdx.x >> 5;
    float invtau = 1.f / (expf(log_tau[0]) + 1e-8f);
    if (threadIdx.x < KNN) {
        sidx[threadIdx.x] = idx[(size_t)row * KNN + threadIdx.x];
        sgeo[threadIdx.x] = -dist[(size_t)row * KNN + threadIdx.x] * invtau;
    }
    __syncthreads();
    int b = row >> 11;
    const float* qp = qkv + (size_t)row * 2304 + h * HDIM;
    float q0 = qp[2 * lane], q1 = qp[2 * lane + 1];
    const float* kb = qkv + (size_t)b * NTOK * 2304 + 768 + h * HDIM;
    const float* vb = qkv + (size_t)b * NTOK * 2304 + 1536 + h * HDIM;
    float myscore = 0.f;
#pragma unroll
    for (int j0 = 0; j0 < KNN; j0 += 8) {
        float ka[8], kc[8];
#pragma unroll
        for (int u = 0; u < 8; u++) {
            const float2 kv2 = *(const float2*)(kb + (size_t)sidx[j0 + u] * 2304 + 2 * lane);
            ka[u] = kv2.x; kc[u] = kv2.y;
        }
#pragma unroll
        for (int u = 0; u < 8; u++) {
            float p = q0 * ka[u] + q1 * kc[u];
#pragma unroll
            for (int o = 16; o; o >>= 1) p += __shfl_xor_sync(0xffffffffu, p, o);
            if (lane == j0 + u) myscore = p * 0.125f + sgeo[j0 + u];
        }
    }
    float m = myscore;
#pragma unroll
    for (int o = 16; o; o >>= 1) m = fmaxf(m, __shfl_xor_sync(0xffffffffu, m, o));
    float e = expf(myscore - m);
    float s = e;
#pragma unroll
    for (int o = 16; o; o >>= 1) s += __shfl_xor_sync(0xffffffffu, s, o);
    float p = e / s;
    float v0 = 0.f, v1 = 0.f;
#pragma unroll
    for (int j0 = 0; j0 < KNN; j0 += 8) {
        float va[8], vc[8];
#pragma unroll
        for (int u = 0; u < 8; u++) {
            const float2 vv2 = *(const float2*)(vb + (size_t)sidx[j0 + u] * 2304 + 2 * lane);
            va[u] = vv2.x; vc[u] = vv2.y;
        }
#pragma unroll
        for (int u = 0; u < 8; u++) {
            float pj = __shfl_sync(0xffffffffu, p, j0 + u);
            v0 += pj * va[u]; v1 += pj * vc[u];
        }
    }
    float mx = fmaxf(fabsf(v0), fabsf(v1));
#pragma unroll
    for (int o = 16; o; o >>= 1) mx = fmaxf(mx, __shfl_xor_sync(0xffffffffu, mx, o));
    if (lane == 0) smax[h] = mx;
    __syncthreads();
    if (h == 0) {
        float r = (lane < 12) ? smax[lane] : 0.f;
#pragma unroll
        for (int o = 16; o; o >>= 1) r = fmaxf(r, __shfl_xor_sync(0xffffffffu, r, o));
        if (lane == 0) smax[12] = r;
    }
    __syncthreads();
    float rmax = fmaxf(smax[12], 1e-20f);
    float inv = QMAX / rmax;
    char a1, a0, b1c, b0c;
    quant_limbs(v0, inv, a1, a0);
    quant_limbs(v1, inv, b1c, b0c);
    size_t oi = (size_t)row * DIMV + h * HDIM + 2 * lane;
    *(char2*)(o1 + oi) = make_char2(a1, b1c);
    *(char2*)(o0 + oi) = make_char2(a0, b0c);
    if (threadIdx.x == 0) sA[row] = rmax / QMAX;
}

// ---------------------------------------------------------------------------
extern "C" void kernel_launch(void* const* d_in, const int* in_sizes, int n_in,
                              void* d_out, int out_size)
{
    const float* x    = (const float*)d_in[0];
    const float* pos  = (const float*)d_in[1];
    const float* c    = (const float*)d_in[2];
    const float* temb = (const float*)d_in[3];
    const float* Wq = (const float*)d_in[4],  *bq = (const float*)d_in[5];
    const float* Wk = (const float*)d_in[6],  *bk = (const float*)d_in[7];
    const float* Wv = (const float*)d_in[8],  *bv = (const float*)d_in[9];
    const float* Wo = (const float*)d_in[10], *bo = (const float*)d_in[11];
    const float* W1 = (const float*)d_in[12], *b1 = (const float*)d_in[13];
    const float* W2 = (const float*)d_in[14], *b2 = (const float*)d_in[15];
    const float* g1 = (const float*)d_in[16], *be1 = (const float*)d_in[17];
    const float* g2 = (const float*)d_in[18], *be2 = (const float*)d_in[19];
    const float* log_tau = (const float*)d_in[20];
    float* out = (float*)d_out;

    char* arena; cudaGetSymbolAddress((void**)&arena, g_arena);
    int* idxp;   cudaGetSymbolAddress((void**)&idxp, g_idx);
    float* distp;cudaGetSymbolAddress((void**)&distp, g_dist);

    char* p = arena;
    auto carve = [&](size_t bytes) { char* r = p; p += (bytes + 127) & ~(size_t)127; return r; };
    char* h1   = carve((size_t)MROWS * 768);
    char* h0   = carve((size_t)MROWS * 768);
    char* att1 = carve((size_t)MROWS * 768);
    char* att0 = carve((size_t)MROWS * 768);
    char* h21  = carve((size_t)MROWS * 768);
    char* h20  = carve((size_t)MROWS * 768);
    char* ffn1 = carve((size_t)MROWS * 3072);
    char* ffn0 = carve((size_t)MROWS * 3072);
    char* wqkv1 = carve((size_t)2304 * 768);
    char* wqkv0 = carve((size_t)2304 * 768);
    char* wo1  = carve((size_t)768 * 768);
    char* wo0  = carve((size_t)768 * 768);
    char* w11  = carve((size_t)3072 * 768);
    char* w10  = carve((size_t)3072 * 768);
    char* w21  = carve((size_t)768 * 3072);
    char* w20  = carve((size_t)768 * 3072);
    float* qkv   = (float*)carve((size_t)MROWS * 2304 * 4);
    float* x2    = (float*)carve((size_t)MROWS * 768 * 4);
    float* ffn_f = (float*)carve((size_t)MROWS * 3072 * 4);
    float* partial = (float*)carve(8 * PSTRIDE * 4);
    float* sAh   = (float*)carve(MROWS * 4);
    float* sAatt = (float*)carve(MROWS * 4);
    float* sAh2  = (float*)carve(MROWS * 4);
    float* sAffn = (float*)carve(MROWS * 4);
    float* sBqkv = (float*)carve(2304 * 4);
    float* sBo   = (float*)carve(768 * 4);
    float* sB1   = (float*)carve(3072 * 4);
    float* sB2   = (float*)carve(768 * 4);
    float* bqkv  = (float*)carve(2304 * 4);

    cudaFuncSetAttribute(s8_gemm_kernel,
                         cudaFuncAttributeMaxDynamicSharedMemorySize, GEMM_SMEM);

    // launches 1-3, then topk as launch 4 (= ncu capture slot)
    ln_quant_kernel<<<MROWS, 384>>>(x, g1, be1, temb, h1, h0, sAh);
    wpmax_qkv_kernel<<<dim3(9, 8), 256>>>(Wq, Wk, Wv, bq, bk, bv, partial, bqkv);
    wquantT3_kernel<<<dim3(24, 24, 3), 256>>>(Wq, Wk, Wv, partial, sBqkv, wqkv1, wqkv0);
    topk_kernel<<<MROWS, 256>>>(pos, c, idxp, distp);

    s8_gemm_kernel<<<dim3(18, 32), 512, GEMM_SMEM>>>(h1, h0, wqkv1, wqkv0,
        sAh, sBqkv, bqkv, nullptr, qkv, 2304, 768, 0);
    attn_quant_kernel<<<MROWS, 384>>>(qkv, idxp, distp, log_tau, att1, att0, sAatt);

    wpmax_rest_kernel<<<dim3(18, 8), 256>>>(Wo, W1, W2, partial);
    wquantT_kernel<<<dim3(24, 24), 256>>>(Wo, partial, 2304, sBo, wo1, wo0, 768, 768);
    wquantT_kernel<<<dim3(96, 24), 256>>>(W1, partial, 3072, sB1, w11, w10, 3072, 768);
    wquantT_kernel<<<dim3(24, 96), 256>>>(W2, partial, 6144, sB2, w21, w20, 768, 3072);

    // x2 = x + att @ Wo
    s8_gemm_kernel<<<dim3(6, 32), 512, GEMM_SMEM>>>(att1, att0, wo1, wo0,
        sAatt, sBo, bo, x, x2, 768, 768, 0);
    ln_quant_kernel<<<MROWS, 384>>>(x2, g2, be2, nullptr, h21, h20, sAh2);

    // ffn_f = gelu(h2 @ W1)
    s8_gemm_kernel<<<dim3(24, 32), 512, GEMM_SMEM>>>(h21, h20, w11, w10,
        sAh2, sB1, b1, nullptr, ffn_f, 3072, 768, 1);
    ffn_quant_kernel<<<MROWS, 256>>>(ffn_f, ffn1, ffn0, sAffn);

    // out = x2 + ffn @ W2
    s8_gemm_kernel<<<dim3(6, 32), 512, GEMM_SMEM>>>(ffn1, ffn0, w21, w20,
        sAffn, sB2, b2, x2, out, 768, 3072, 0);
}

// round 10
// speedup vs baseline: 1.6791x; 1.1033x over previous
#include <cuda_runtime.h>
#include <cuda_bf16.h>
#include <math.h>
#include <stdint.h>

#define NTOK 2048
#define BATCH 2
#define DIMV 768
#define NHEAD 12
#define HDIM 64
#define KNN 32
#define DFF 3072
#define MROWS 4096   // BATCH*NTOK
#define QMAX 16256.0f
#define PSTRIDE 8192

// ---------------------------------------------------------------------------
#define ARENA_BYTES 172000000ull
__device__ __align__(128) char g_arena[ARENA_BYTES];
__device__ int   g_idx[MROWS * KNN];
__device__ float g_dist[MROWS * KNN];

// ---------------------------------------------------------------------------
__device__ __forceinline__ float gelu_f(float v) {
    return 0.5f * v * (1.f + erff(v * 0.70710678118654752f));
}
__device__ __forceinline__ void quant_limbs(float v, float inv_s, char& q1c, char& q0c) {
    int q = __float2int_rn(v * inv_s);
    q = max(-16256, min(16256, q));
    int q1 = (q + 64) >> 7;
    int q0 = q - (q1 << 7);
    q1c = (char)q1; q0c = (char)q0;
}

// ---------------------------------------------------------------------------
// parallel per-column absmax, 8 K-chunks; qkv variant also concats bias
__global__ void __launch_bounds__(256) wpmax_qkv_kernel(
    const float* __restrict__ Wq, const float* __restrict__ Wk, const float* __restrict__ Wv,
    const float* __restrict__ bq, const float* __restrict__ bk, const float* __restrict__ bv,
    float* __restrict__ partial, float* __restrict__ bqkv)
{
    int col = blockIdx.x * 256 + threadIdx.x;        // 0..2303
    int w = col / 768, c = col - w * 768;
    const float* W = (w == 0) ? Wq : (w == 1) ? Wk : Wv;
    int k0 = blockIdx.y * 96;
    float mx = 0.f;
#pragma unroll 8
    for (int k = k0; k < k0 + 96; k++) mx = fmaxf(mx, fabsf(W[(size_t)k * 768 + c]));
    partial[blockIdx.y * PSTRIDE + col] = mx;
    if (blockIdx.y == 0)
        bqkv[col] = ((w == 0) ? bq : (w == 1) ? bk : bv)[c];
}

__global__ void __launch_bounds__(256) wpmax_rest_kernel(
    const float* __restrict__ Wo, const float* __restrict__ W1, const float* __restrict__ W2,
    float* __restrict__ partial)
{
    int j = blockIdx.x * 256 + threadIdx.x;          // 0..4607
    const float* W; int c, K, Nc;
    if (j < 768)       { W = Wo; c = j;        K = 768;  Nc = 768;  }
    else if (j < 3840) { W = W1; c = j - 768;  K = 768;  Nc = 3072; }
    else               { W = W2; c = j - 3840; K = 3072; Nc = 768;  }
    int chunk = K >> 3;
    int k0 = blockIdx.y * chunk;
    float mx = 0.f;
#pragma unroll 8
    for (int k = k0; k < k0 + chunk; k++) mx = fmaxf(mx, fabsf(W[(size_t)k * Nc + c]));
    partial[blockIdx.y * PSTRIDE + 2304 + j] = mx;
}

// transpose+quantize tile; reduces partial->scale inline, writes sB
__device__ __forceinline__ void wq_tile(const float* W, const float* partial,
    int pcolOff, float* sBout, char* o1, char* o0, int Nc, int Kd, int rowOff,
    int n0, int k0, int tid)
{
    __shared__ char s1[32][33], s0[32][33];
    int tx = tid & 31, tyg = tid >> 5;
    int n = n0 + tx;
    float mx = 0.f;
#pragma unroll
    for (int j = 0; j < 8; j++) mx = fmaxf(mx, partial[j * PSTRIDE + pcolOff + n]);
    mx = fmaxf(mx, 1e-20f);
    float inv = QMAX / mx;
    if (k0 == 0 && tyg == 0) sBout[rowOff + n] = mx / QMAX;
#pragma unroll
    for (int j = 0; j < 4; j++) {
        int kl = tyg * 4 + j;
        float v = W[(size_t)(k0 + kl) * Nc + n];
        quant_limbs(v, inv, s1[kl][tx], s0[kl][tx]);
    }
    __syncthreads();
#pragma unroll
    for (int j = 0; j < 4; j++) {
        int nl = tyg * 4 + j;
        size_t oidx = (size_t)(rowOff + n0 + nl) * Kd + k0 + tx;
        o1[oidx] = s1[tx][nl];
        o0[oidx] = s0[tx][nl];
    }
}

__global__ void __launch_bounds__(256) wquantT3_kernel(
    const float* __restrict__ Wq, const float* __restrict__ Wk, const float* __restrict__ Wv,
    const float* __restrict__ partial, float* __restrict__ sB,
    char* __restrict__ o1, char* __restrict__ o0)
{
    int z = blockIdx.z;
    const float* W = (z == 0) ? Wq : (z == 1) ? Wk : Wv;
    wq_tile(W, partial, z * 768, sB, o1, o0, 768, 768, z * 768,
            blockIdx.x * 32, blockIdx.y * 32, threadIdx.x);
}

__global__ void __launch_bounds__(256) wquantT_kernel(
    const float* __restrict__ W, const float* __restrict__ partial, int pcolOff,
    float* __restrict__ sB, char* __restrict__ o1, char* __restrict__ o0, int Nc, int Kd)
{
    wq_tile(W, partial, pcolOff, sB, o1, o0, Nc, Kd, 0,
            blockIdx.x * 32, blockIdx.y * 32, threadIdx.x);
}

// ---------------------------------------------------------------------------
// LayerNorm (+time emb) -> int8 limb planes + per-row scale
__global__ void __launch_bounds__(384) ln_quant_kernel(const float* __restrict__ x,
    const float* __restrict__ g, const float* __restrict__ be,
    const float* __restrict__ temb, char* __restrict__ o1, char* __restrict__ o0,
    float* __restrict__ sA)
{
    __shared__ float sb[13];
    int row = blockIdx.x, tid = threadIdx.x;
    int lane = tid & 31, w = tid >> 5;
    float2 xv = *(const float2*)(x + (size_t)row * DIMV + 2 * tid);
    float s = xv.x + xv.y;
#pragma unroll
    for (int o = 16; o; o >>= 1) s += __shfl_xor_sync(0xffffffffu, s, o);
    if (lane == 0) sb[w] = s;
    __syncthreads();
    if (w == 0) {
        float r = (lane < 12) ? sb[lane] : 0.f;
#pragma unroll
        for (int o = 16; o; o >>= 1) r += __shfl_xor_sync(0xffffffffu, r, o);
        if (lane == 0) sb[12] = r;
    }
    __syncthreads();
    float mu = sb[12] * (1.0f / DIMV);
    float dx = xv.x - mu, dy = xv.y - mu;
    float vs = dx * dx + dy * dy;
    __syncthreads();
#pragma unroll
    for (int o = 16; o; o >>= 1) vs += __shfl_xor_sync(0xffffffffu, vs, o);
    if (lane == 0) sb[w] = vs;
    __syncthreads();
    if (w == 0) {
        float r = (lane < 12) ? sb[lane] : 0.f;
#pragma unroll
        for (int o = 16; o; o >>= 1) r += __shfl_xor_sync(0xffffffffu, r, o);
        if (lane == 0) sb[12] = r;
    }
    __syncthreads();
    float inv = rsqrtf(sb[12] * (1.0f / DIMV) + 1e-5f);
    int b = row >> 11;
    int i0 = 2 * tid;
    float v0 = dx * inv * g[i0] + be[i0];
    float v1 = dy * inv * g[i0 + 1] + be[i0 + 1];
    if (temb) { v0 += temb[b * DIMV + i0]; v1 += temb[b * DIMV + i0 + 1]; }
    float mx = fmaxf(fabsf(v0), fabsf(v1));
    __syncthreads();
#pragma unroll
    for (int o = 16; o; o >>= 1) mx = fmaxf(mx, __shfl_xor_sync(0xffffffffu, mx, o));
    if (lane == 0) sb[w] = mx;
    __syncthreads();
    if (w == 0) {
        float r = (lane < 12) ? sb[lane] : 0.f;
#pragma unroll
        for (int o = 16; o; o >>= 1) r = fmaxf(r, __shfl_xor_sync(0xffffffffu, r, o));
        if (lane == 0) sb[12] = r;
    }
    __syncthreads();
    float rmax = fmaxf(sb[12], 1e-20f);
    float invs = QMAX / rmax;
    char a1, a0, b1, b0;
    quant_limbs(v0, invs, a1, a0);
    quant_limbs(v1, invs, b1, b0);
    size_t oi = (size_t)row * DIMV + i0;
    *(char2*)(o1 + oi) = make_char2(a1, b1);
    *(char2*)(o0 + oi) = make_char2(a0, b0);
    if (tid == 0) sA[row] = rmax / QMAX;
}

// ---------------------------------------------------------------------------
// int8 limb GEMM (3-pass). Block 128x128, 512 thr, BK=64, 4-stage cp.async.
// ---------------------------------------------------------------------------
#define O_A1 0
#define O_A0 8192
#define O_B1 16384
#define O_B0 24576
#define STG_BYTES 32768
#define GEMM_SMEM (4 * STG_BYTES)   // 128KB

__device__ __forceinline__ void cp16s(uint32_t sdst, const void* src) {
    asm volatile("cp.async.cg.shared.global [%0], [%1], 16;" :: "r"(sdst), "l"(src));
}
#define LDSM4(r, addr)                                                        \
    asm volatile("ldmatrix.sync.aligned.m8n8.x4.shared.b16 {%0,%1,%2,%3}, [%4];" \
        : "=r"((r)[0]), "=r"((r)[1]), "=r"((r)[2]), "=r"((r)[3]) : "r"(addr))
#define MMA_S8(d, a, b0, b1)                                                  \
    asm volatile(                                                             \
        "mma.sync.aligned.m16n8k32.row.col.s32.s8.s8.s32 "                    \
        "{%0,%1,%2,%3},{%4,%5,%6,%7},{%8,%9},{%0,%1,%2,%3};"                  \
        : "+r"((d)[0]), "+r"((d)[1]), "+r"((d)[2]), "+r"((d)[3])              \
        : "r"((a)[0]), "r"((a)[1]), "r"((a)[2]), "r"((a)[3]), "r"(b0), "r"(b1))

__global__ void __launch_bounds__(512, 1) s8_gemm_kernel(
    const char* __restrict__ A1, const char* __restrict__ A0,
    const char* __restrict__ B1, const char* __restrict__ B0,
    const float* __restrict__ sA, const float* __restrict__ sB,
    const float* __restrict__ bias, const float* __restrict__ res,
    float* __restrict__ Cf, int Nc, int K, int act)
{
    extern __shared__ __align__(128) char smc[];
    const int tid = threadIdx.x;
    const int warp = tid >> 5, lane = tid & 31;
    const int wm = warp & 3, wn = warp >> 2;
    const int g = lane >> 2, t = lane & 3;
    const int bm = blockIdx.y * 128, bn = blockIdx.x * 128;
    const int nk = K >> 6;

    uint32_t sbase;
    asm("{ .reg .u64 tt; cvta.to.shared.u64 tt, %1; cvt.u32.u64 %0, tt; }"
        : "=r"(sbase) : "l"(smc));

    const int arl = lane & 15, aqb = lane >> 4;
    const int arsw = (arl >> 1) & 3;
    uint32_t aoff[2], aq[2];
#pragma unroll
    for (int mi = 0; mi < 2; mi++)
        aoff[mi] = (uint32_t)(wm * 32 + mi * 16 + arl) * 64u;
#pragma unroll
    for (int ks = 0; ks < 2; ks++)
        aq[ks] = (uint32_t)(((2 * ks + aqb) ^ arsw) << 4);
    const int nrl = (lane & 7) + ((lane >> 4) << 3);
    const int bqb = (lane >> 3) & 1;
    const int brsw = (nrl >> 1) & 3;
    uint32_t boff[2], bq[2];
#pragma unroll
    for (int ni = 0; ni < 2; ni++)
        boff[ni] = (uint32_t)(wn * 32 + ni * 16 + nrl) * 64u;
#pragma unroll
    for (int ks = 0; ks < 2; ks++)
        bq[ks] = (uint32_t)(((2 * ks + bqb) ^ brsw) << 4);

    int hh[2][2][2][4], cx[2][2][2][4];
#pragma unroll
    for (int mi = 0; mi < 2; mi++)
#pragma unroll
        for (int ni = 0; ni < 2; ni++)
#pragma unroll
            for (int pr = 0; pr < 2; pr++)
#pragma unroll
                for (int e = 0; e < 4; e++) { hh[mi][ni][pr][e] = 0; cx[mi][ni][pr][e] = 0; }

    auto load_stage = [&](int buf, int it) {
        if (it < nk) {
            uint32_t st = sbase + buf * STG_BYTES;
            int kb = it * 64;
            int m = tid >> 2, q = tid & 3;
            uint32_t woff = (uint32_t)(m * 64 + ((q ^ ((m >> 1) & 3)) << 4));
            size_t ga = (size_t)(bm + m) * K + kb + q * 16;
            cp16s(st + O_A1 + woff, A1 + ga);
            cp16s(st + O_A0 + woff, A0 + ga);
            size_t gb = (size_t)(bn + m) * K + kb + q * 16;
            cp16s(st + O_B1 + woff, B1 + gb);
            cp16s(st + O_B0 + woff, B0 + gb);
        }
        asm volatile("cp.async.commit_group;");
    };

    load_stage(0, 0);
    load_stage(1, 1);
    load_stage(2, 2);

    for (int it = 0; it < nk; it++) {
        asm volatile("cp.async.wait_group 2;");
        __syncthreads();
        load_stage((it + 3) & 3, it + 3);

        uint32_t st = sbase + (it & 3) * STG_BYTES;
#pragma unroll
        for (int ks = 0; ks < 2; ks++) {
            uint32_t fA1[2][4], fA0[2][4], fB1[2][4], fB0[2][4];
#pragma unroll
            for (int mi = 0; mi < 2; mi++)
                LDSM4(fA1[mi], st + O_A1 + aoff[mi] + aq[ks]);
#pragma unroll
            for (int ni = 0; ni < 2; ni++)
                LDSM4(fB1[ni], st + O_B1 + boff[ni] + bq[ks]);
#pragma unroll
            for (int mi = 0; mi < 2; mi++)
#pragma unroll
                for (int ni = 0; ni < 2; ni++)
#pragma unroll
                    for (int pr = 0; pr < 2; pr++)
                        MMA_S8(hh[mi][ni][pr], fA1[mi], fB1[ni][2 * pr], fB1[ni][2 * pr + 1]);
#pragma unroll
            for (int ni = 0; ni < 2; ni++)
                LDSM4(fB0[ni], st + O_B0 + boff[ni] + bq[ks]);
#pragma unroll
            for (int mi = 0; mi < 2; mi++)
#pragma unroll
                for (int ni = 0; ni < 2; ni++)
#pragma unroll
                    for (int pr = 0; pr < 2; pr++)
                        MMA_S8(cx[mi][ni][pr], fA1[mi], fB0[ni][2 * pr], fB0[ni][2 * pr + 1]);
#pragma unroll
            for (int mi = 0; mi < 2; mi++)
                LDSM4(fA0[mi], st + O_A0 + aoff[mi] + aq[ks]);
#pragma unroll
            for (int mi = 0; mi < 2; mi++)
#pragma unroll
                for (int ni = 0; ni < 2; ni++)
#pragma unroll
                    for (int pr = 0; pr < 2; pr++)
                        MMA_S8(cx[mi][ni][pr], fA0[mi], fB1[ni][2 * pr], fB1[ni][2 * pr + 1]);
        }
    }

#pragma unroll
    for (int mi = 0; mi < 2; mi++) {
#pragma unroll
        for (int ni = 0; ni < 2; ni++) {
#pragma unroll
            for (int pr = 0; pr < 2; pr++) {
                int col = bn + wn * 32 + ni * 16 + pr * 8 + 2 * t;
                float2 sb2 = *(const float2*)(sB + col);
                float2 bb = *(const float2*)(bias + col);
#pragma unroll
                for (int hf = 0; hf < 2; hf++) {
                    int r = bm + wm * 32 + mi * 16 + g + hf * 8;
                    float sa = sA[r];
                    float vx = sa * sb2.x * (16384.f * (float)hh[mi][ni][pr][2 * hf]
                              + 128.f * (float)cx[mi][ni][pr][2 * hf]) + bb.x;
                    float vy = sa * sb2.y * (16384.f * (float)hh[mi][ni][pr][2 * hf + 1]
                              + 128.f * (float)cx[mi][ni][pr][2 * hf + 1]) + bb.y;
                    if (act) { vx = gelu_f(vx); vy = gelu_f(vy); }
                    if (res) {
                        const float2 rr = *(const float2*)(res + (size_t)r * Nc + col);
                        vx += rr.x; vy += rr.y;
                    }
                    float2 o; o.x = vx; o.y = vy;
                    *(float2*)(Cf + (size_t)r * Nc + col) = o;
                }
            }
        }
    }
}

// ---------------------------------------------------------------------------
// ffn row quant
__global__ void __launch_bounds__(256) ffn_quant_kernel(const float* __restrict__ f,
    char* __restrict__ o1, char* __restrict__ o0, float* __restrict__ sA)
{
    __shared__ float sb[9];
    int row = blockIdx.x, tid = threadIdx.x;
    int lane = tid & 31, w = tid >> 5;
    const float4* base = (const float4*)(f + (size_t)row * DFF);
    float mx = 0.f;
#pragma unroll
    for (int i = 0; i < 3; i++) {
        float4 v = base[tid + i * 256];
        mx = fmaxf(mx, fmaxf(fmaxf(fabsf(v.x), fabsf(v.y)), fmaxf(fabsf(v.z), fabsf(v.w))));
    }
#pragma unroll
    for (int o = 16; o; o >>= 1) mx = fmaxf(mx, __shfl_xor_sync(0xffffffffu, mx, o));
    if (lane == 0) sb[w] = mx;
    __syncthreads();
    if (w == 0) {
        float r = (lane < 8) ? sb[lane] : 0.f;
#pragma unroll
        for (int o = 4; o; o >>= 1) r = fmaxf(r, __shfl_xor_sync(0xffffffffu, r, o));
        if (lane == 0) sb[8] = r;
    }
    __syncthreads();
    float rmax = fmaxf(sb[8], 1e-20f);
    float inv = QMAX / rmax;
    uint32_t* p1 = (uint32_t*)(o1 + (size_t)row * DFF);
    uint32_t* p0 = (uint32_t*)(o0 + (size_t)row * DFF);
#pragma unroll
    for (int i = 0; i < 3; i++) {
        float4 v = base[tid + i * 256];
        char a1, a0, b1, b0, c1, c0, d1, d0;
        quant_limbs(v.x, inv, a1, a0);
        quant_limbs(v.y, inv, b1, b0);
        quant_limbs(v.z, inv, c1, c0);
        quant_limbs(v.w, inv, d1, d0);
        p1[tid + i * 256] = (uint32_t)(uint8_t)a1 | ((uint32_t)(uint8_t)b1 << 8)
                          | ((uint32_t)(uint8_t)c1 << 16) | ((uint32_t)(uint8_t)d1 << 24);
        p0[tid + i * 256] = (uint32_t)(uint8_t)a0 | ((uint32_t)(uint8_t)b0 << 8)
                          | ((uint32_t)(uint8_t)c0 << 16) | ((uint32_t)(uint8_t)d0 << 24);
    }
    if (tid == 0) sA[row] = rmax / QMAX;
}

// ---------------------------------------------------------------------------
// Poincare top-KNN: warp-synchronous sorted-run merge (no barriers in loop).
// key64 = (float_bits << 32) | idx  — unsigned order == (val, idx) lexicographic
// for the positive args here, so selection order matches lax.top_k exactly.
// ---------------------------------------------------------------------------
__device__ __forceinline__ void ce64(unsigned long long& a, unsigned long long& b) {
    unsigned long long lo = min(a, b), hi = max(a, b);
    a = lo; b = hi;
}

__global__ void __launch_bounds__(256) topk_kernel(const float* __restrict__ pos,
    const float* __restrict__ cptr, int* __restrict__ idxo, float* __restrict__ disto)
{
    __shared__ unsigned long long skv[NTOK];
    int row = blockIdx.x, tid = threadIdx.x;
    int b = row >> 11, i = row & (NTOK - 1);
    float c = cptr[0];
    float inv_sqc = rsqrtf(c);
    const float* pb = pos + (size_t)b * NTOK * 2;
    float yx = pb[i * 2], yy = pb[i * 2 + 1];
    float denY = 1.f - c * (yx * yx + yy * yy);

    // phase 1: 8 keys per thread, sort (Batcher 19 CE), spill sorted runs
    unsigned long long k[8];
#pragma unroll
    for (int u = 0; u < 8; u++) {
        int j = tid + u * 256;
        float2 pj = *(const float2*)(pb + j * 2);
        float dx = pj.x - yx, dy = pj.y - yy;
        float num = 2.f * c * (dx * dx + dy * dy);
        float den = (1.f - c * (pj.x * pj.x + pj.y * pj.y)) * denY;
        float v = fmaxf(1.f + num / (den + 1e-8f), 1.f);
        k[u] = ((unsigned long long)__float_as_uint(v) << 32) | (unsigned)j;
    }
    ce64(k[0],k[1]); ce64(k[2],k[3]); ce64(k[4],k[5]); ce64(k[6],k[7]);
    ce64(k[0],k[2]); ce64(k[1],k[3]); ce64(k[4],k[6]); ce64(k[5],k[7]);
    ce64(k[1],k[2]); ce64(k[5],k[6]);
    ce64(k[0],k[4]); ce64(k[1],k[5]); ce64(k[2],k[6]); ce64(k[3],k[7]);
    ce64(k[2],k[4]); ce64(k[3],k[5]);
    ce64(k[1],k[2]); ce64(k[3],k[4]); ce64(k[5],k[6]);
#pragma unroll
    for (int u = 0; u < 8; u++) skv[tid * 8 + u] = k[u];
    __syncthreads();
    if (tid >= 32) return;                 // warps 1-7 retire

    // phase 2: warp 0, lane owns runs lane*8 .. lane*8+7
    int lane = tid;
    unsigned long long head[8];
    int ptr[8];
#pragma unroll
    for (int h = 0; h < 8; h++) {
        head[h] = skv[(lane * 8 + h) * 8];
        ptr[h] = 0;
    }
    unsigned long long lmin = head[0]; int lh = 0;
#pragma unroll
    for (int h = 1; h < 8; h++)
        if (head[h] < lmin) { lmin = head[h]; lh = h; }

    unsigned long long mykey = 0xFFFFFFFFFFFFFFFFull;
    for (int sel = 0; sel < KNN; sel++) {
        unsigned long long bk = lmin; int bl = lane;
#pragma unroll
        for (int o = 16; o; o >>= 1) {
            unsigned long long ok = __shfl_xor_sync(0xffffffffu, bk, o);
            int ol = __shfl_xor_sync(0xffffffffu, bl, o);
            if (ok < bk) { bk = ok; bl = ol; }
        }
        if (lane == sel) mykey = bk;
        if (lane == bl) {
            int pp = ++ptr[lh];
            head[lh] = (pp < 8) ? skv[(lane * 8 + lh) * 8 + pp]
                                : 0xFFFFFFFFFFFFFFFFull;
            lmin = head[0]; lh = 0;
#pragma unroll
            for (int h = 1; h < 8; h++)
                if (head[h] < lmin) { lmin = head[h]; lh = h; }
        }
    }
    float v = __uint_as_float((unsigned)(mykey >> 32));
    idxo[(size_t)row * KNN + lane] = (int)(unsigned)(mykey & 0xFFFFFFFFull);
    disto[(size_t)row * KNN + lane] = acoshf(v) * inv_sqc;
}

// ---------------------------------------------------------------------------
// kNN attention: batched gather loads (MLP 16), int8-limb output + row scale
__global__ void __launch_bounds__(384) attn_quant_kernel(const float* __restrict__ qkv,
    const int* __restrict__ idx, const float* __restrict__ dist,
    const float* __restrict__ log_tau,
    char* __restrict__ o1, char* __restrict__ o0, float* __restrict__ sA)
{
    __shared__ int sidx[KNN];
    __shared__ float sgeo[KNN];
    __shared__ float smax[13];
    int row = blockIdx.x;
    int lane = threadIdx.x & 31, h = threadIdx.x >> 5;
    float invtau = 1.f / (expf(log_tau[0]) + 1e-8f);
    if (threadIdx.x < KNN) {
        sidx[threadIdx.x] = idx[(size_t)row * KNN + threadIdx.x];
        sgeo[threadIdx.x] = -dist[(size_t)row * KNN + threadIdx.x] * invtau;
    }
    __syncthreads();
    int b = row >> 11;
    const float* qp = qkv + (size_t)row * 2304 + h * HDIM;
    float q0 = qp[2 * lane], q1 = qp[2 * lane + 1];
    const float* kb = qkv + (size_t)b * NTOK * 2304 + 768 + h * HDIM;
    const float* vb = qkv + (size_t)b * NTOK * 2304 + 1536 + h * HDIM;
    float myscore = 0.f;
#pragma unroll
    for (int j0 = 0; j0 < KNN; j0 += 8) {
        float ka[8], kc[8];
#pragma unroll
        for (int u = 0; u < 8; u++) {
            const float2 kv2 = *(const float2*)(kb + (size_t)sidx[j0 + u] * 2304 + 2 * lane);
            ka[u] = kv2.x; kc[u] = kv2.y;
        }
#pragma unroll
        for (int u = 0; u < 8; u++) {
            float p = q0 * ka[u] + q1 * kc[u];
#pragma unroll
            for (int o = 16; o; o >>= 1) p += __shfl_xor_sync(0xffffffffu, p, o);
            if (lane == j0 + u) myscore = p * 0.125f + sgeo[j0 + u];
        }
    }
    float m = myscore;
#pragma unroll
    for (int o = 16; o; o >>= 1) m = fmaxf(m, __shfl_xor_sync(0xffffffffu, m, o));
    float e = expf(myscore - m);
    float s = e;
#pragma unroll
    for (int o = 16; o; o >>= 1) s += __shfl_xor_sync(0xffffffffu, s, o);
    float p = e / s;
    float v0 = 0.f, v1 = 0.f;
#pragma unroll
    for (int j0 = 0; j0 < KNN; j0 += 8) {
        float va[8], vc[8];
#pragma unroll
        for (int u = 0; u < 8; u++) {
            const float2 vv2 = *(const float2*)(vb + (size_t)sidx[j0 + u] * 2304 + 2 * lane);
            va[u] = vv2.x; vc[u] = vv2.y;
        }
#pragma unroll
        for (int u = 0; u < 8; u++) {
            float pj = __shfl_sync(0xffffffffu, p, j0 + u);
            v0 += pj * va[u]; v1 += pj * vc[u];
        }
    }
    float mx = fmaxf(fabsf(v0), fabsf(v1));
#pragma unroll
    for (int o = 16; o; o >>= 1) mx = fmaxf(mx, __shfl_xor_sync(0xffffffffu, mx, o));
    if (lane == 0) smax[h] = mx;
    __syncthreads();
    if (h == 0) {
        float r = (lane < 12) ? smax[lane] : 0.f;
#pragma unroll
        for (int o = 16; o; o >>= 1) r = fmaxf(r, __shfl_xor_sync(0xffffffffu, r, o));
        if (lane == 0) smax[12] = r;
    }
    __syncthreads();
    float rmax = fmaxf(smax[12], 1e-20f);
    float inv = QMAX / rmax;
    char a1, a0, b1c, b0c;
    quant_limbs(v0, inv, a1, a0);
    quant_limbs(v1, inv, b1c, b0c);
    size_t oi = (size_t)row * DIMV + h * HDIM + 2 * lane;
    *(char2*)(o1 + oi) = make_char2(a1, b1c);
    *(char2*)(o0 + oi) = make_char2(a0, b0c);
    if (threadIdx.x == 0) sA[row] = rmax / QMAX;
}

// ---------------------------------------------------------------------------
extern "C" void kernel_launch(void* const* d_in, const int* in_sizes, int n_in,
                              void* d_out, int out_size)
{
    const float* x    = (const float*)d_in[0];
    const float* pos  = (const float*)d_in[1];
    const float* c    = (const float*)d_in[2];
    const float* temb = (const float*)d_in[3];
    const float* Wq = (const float*)d_in[4],  *bq = (const float*)d_in[5];
    const float* Wk = (const float*)d_in[6],  *bk = (const float*)d_in[7];
    const float* Wv = (const float*)d_in[8],  *bv = (const float*)d_in[9];
    const float* Wo = (const float*)d_in[10], *bo = (const float*)d_in[11];
    const float* W1 = (const float*)d_in[12], *b1 = (const float*)d_in[13];
    const float* W2 = (const float*)d_in[14], *b2 = (const float*)d_in[15];
    const float* g1 = (const float*)d_in[16], *be1 = (const float*)d_in[17];
    const float* g2 = (const float*)d_in[18], *be2 = (const float*)d_in[19];
    const float* log_tau = (const float*)d_in[20];
    float* out = (float*)d_out;

    char* arena; cudaGetSymbolAddress((void**)&arena, g_arena);
    int* idxp;   cudaGetSymbolAddress((void**)&idxp, g_idx);
    float* distp;cudaGetSymbolAddress((void**)&distp, g_dist);

    char* p = arena;
    auto carve = [&](size_t bytes) { char* r = p; p += (bytes + 127) & ~(size_t)127; return r; };
    char* h1   = carve((size_t)MROWS * 768);
    char* h0   = carve((size_t)MROWS * 768);
    char* att1 = carve((size_t)MROWS * 768);
    char* att0 = carve((size_t)MROWS * 768);
    char* h21  = carve((size_t)MROWS * 768);
    char* h20  = carve((size_t)MROWS * 768);
    char* ffn1 = carve((size_t)MROWS * 3072);
    char* ffn0 = carve((size_t)MROWS * 3072);
    char* wqkv1 = carve((size_t)2304 * 768);
    char* wqkv0 = carve((size_t)2304 * 768);
    char* wo1  = carve((size_t)768 * 768);
    char* wo0  = carve((size_t)768 * 768);
    char* w11  = carve((size_t)3072 * 768);
    char* w10  = carve((size_t)3072 * 768);
    char* w21  = carve((size_t)768 * 3072);
    char* w20  = carve((size_t)768 * 3072);
    float* qkv   = (float*)carve((size_t)MROWS * 2304 * 4);
    float* x2    = (float*)carve((size_t)MROWS * 768 * 4);
    float* ffn_f = (float*)carve((size_t)MROWS * 3072 * 4);
    float* partial = (float*)carve(8 * PSTRIDE * 4);
    float* sAh   = (float*)carve(MROWS * 4);
    float* sAatt = (float*)carve(MROWS * 4);
    float* sAh2  = (float*)carve(MROWS * 4);
    float* sAffn = (float*)carve(MROWS * 4);
    float* sBqkv = (float*)carve(2304 * 4);
    float* sBo   = (float*)carve(768 * 4);
    float* sB1   = (float*)carve(3072 * 4);
    float* sB2   = (float*)carve(768 * 4);
    float* bqkv  = (float*)carve(2304 * 4);

    cudaFuncSetAttribute(s8_gemm_kernel,
                         cudaFuncAttributeMaxDynamicSharedMemorySize, GEMM_SMEM);

    // launches 1-3, then topk as launch 4 (= ncu capture slot)
    ln_quant_kernel<<<MROWS, 384>>>(x, g1, be1, temb, h1, h0, sAh);
    wpmax_qkv_kernel<<<dim3(9, 8), 256>>>(Wq, Wk, Wv, bq, bk, bv, partial, bqkv);
    wquantT3_kernel<<<dim3(24, 24, 3), 256>>>(Wq, Wk, Wv, partial, sBqkv, wqkv1, wqkv0);
    topk_kernel<<<MROWS, 256>>>(pos, c, idxp, distp);

    s8_gemm_kernel<<<dim3(18, 32), 512, GEMM_SMEM>>>(h1, h0, wqkv1, wqkv0,
        sAh, sBqkv, bqkv, nullptr, qkv, 2304, 768, 0);
    attn_quant_kernel<<<MROWS, 384>>>(qkv, idxp, distp, log_tau, att1, att0, sAatt);

    wpmax_rest_kernel<<<dim3(18, 8), 256>>>(Wo, W1, W2, partial);
    wquantT_kernel<<<dim3(24, 24), 256>>>(Wo, partial, 2304, sBo, wo1, wo0, 768, 768);
    wquantT_kernel<<<dim3(96, 24), 256>>>(W1, partial, 3072, sB1, w11, w10, 3072, 768);
    wquantT_kernel<<<dim3(24, 96), 256>>>(W2, partial, 6144, sB2, w21, w20, 768, 3072);

    // x2 = x + att @ Wo
    s8_gemm_kernel<<<dim3(6, 32), 512, GEMM_SMEM>>>(att1, att0, wo1, wo0,
        sAatt, sBo, bo, x, x2, 768, 768, 0);
    ln_quant_kernel<<<MROWS, 384>>>(x2, g2, be2, nullptr, h21, h20, sAh2);

    // ffn_f = gelu(h2 @ W1)
    s8_gemm_kernel<<<dim3(24, 32), 512, GEMM_SMEM>>>(h21, h20, w11, w10,
        sAh2, sB1, b1, nullptr, ffn_f, 3072, 768, 1);
    ffn_quant_kernel<<<MROWS, 256>>>(ffn_f, ffn1, ffn0, sAffn);

    // out = x2 + ffn @ W2
    s8_gemm_kernel<<<dim3(6, 32), 512, GEMM_SMEM>>>(ffn1, ffn0, w21, w20,
        sAffn, sB2, b2, x2, out, 768, 3072, 0);
}